// round 1
// baseline (speedup 1.0000x reference)
#include <cuda_runtime.h>
#include <cstddef>

#define DM 1024
#define HEADS 16
#define HD 64
#define B_ 2
#define S_ 2048
#define MTOT 4096   // B*S

// Scratch (allocation-free rule: __device__ globals)
__device__ float g_q[MTOT * DM];
__device__ float g_k[MTOT * DM];
__device__ float g_v[MTOT * DM];
__device__ float g_ctx[MTOT * DM];

// ---------------------------------------------------------------------------
// SGEMM: C = A @ W + bias, with gating epilogue.
// MODE 0/1/2: A = X, C = g_q/g_k/g_v, epilogue: C = (A@W + b) * gate[m]
// MODE 3:     A = g_ctx, C = out,     epilogue: C = x*(1-g) + (A@W + b)*g
// Tiles: BM=BN=128, BK=16, 256 threads, 8x8 per thread (4+4 split frags).
// ---------------------------------------------------------------------------
template <int MODE>
__global__ __launch_bounds__(256) void sgemm_k(
    const float* __restrict__ X, const float* __restrict__ W,
    const float* __restrict__ bias, const int* __restrict__ gate,
    float* __restrict__ Cout)
{
    __shared__ float As[16][128];
    __shared__ float Bs[16][128];

    const float* A = (MODE == 3) ? (const float*)g_ctx : X;
    float* C;
    if (MODE == 0)      C = g_q;
    else if (MODE == 1) C = g_k;
    else if (MODE == 2) C = g_v;
    else                C = Cout;

    const int tid = threadIdx.x;
    const int m0 = blockIdx.y * 128;
    const int n0 = blockIdx.x * 128;
    const int tx = tid & 15;       // 0..15 -> col groups
    const int ty = tid >> 4;       // 0..15 -> row groups

    // global->smem load indices
    const int ar = tid >> 2;            // 0..63  (A rows, +64 for second half)
    const int ac = (tid & 3) << 2;      // 0,4,8,12 (A k-cols, float4)
    const int brow = tid >> 5;          // 0..7   (B k-rows, +8 for second)
    const int bcol = (tid & 31) << 2;   // 0..124 (B n-cols, float4)

    const float* Ap = A + (size_t)(m0 + ar) * DM + ac;
    const float* Wp = W + (size_t)brow * DM + n0 + bcol;

    float acc[8][8];
#pragma unroll
    for (int i = 0; i < 8; i++)
#pragma unroll
        for (int j = 0; j < 8; j++) acc[i][j] = 0.f;

    for (int k0 = 0; k0 < DM; k0 += 16) {
        float4 a0 = *(const float4*)(Ap + k0);
        float4 a1 = *(const float4*)(Ap + (size_t)64 * DM + k0);
        float4 b0 = *(const float4*)(Wp + (size_t)k0 * DM);
        float4 b1 = *(const float4*)(Wp + (size_t)(k0 + 8) * DM);
        __syncthreads();
        As[ac + 0][ar] = a0.x; As[ac + 1][ar] = a0.y;
        As[ac + 2][ar] = a0.z; As[ac + 3][ar] = a0.w;
        As[ac + 0][ar + 64] = a1.x; As[ac + 1][ar + 64] = a1.y;
        As[ac + 2][ar + 64] = a1.z; As[ac + 3][ar + 64] = a1.w;
        *(float4*)&Bs[brow][bcol]     = b0;
        *(float4*)&Bs[brow + 8][bcol] = b1;
        __syncthreads();
#pragma unroll
        for (int kk = 0; kk < 16; kk++) {
            float av[8], bv[8];
            *(float4*)&av[0] = *(const float4*)&As[kk][ty * 4];
            *(float4*)&av[4] = *(const float4*)&As[kk][64 + ty * 4];
            *(float4*)&bv[0] = *(const float4*)&Bs[kk][tx * 4];
            *(float4*)&bv[4] = *(const float4*)&Bs[kk][64 + tx * 4];
#pragma unroll
            for (int i = 0; i < 8; i++)
#pragma unroll
                for (int j = 0; j < 8; j++)
                    acc[i][j] = fmaf(av[i], bv[j], acc[i][j]);
        }
    }

    // Epilogue
#pragma unroll
    for (int rh = 0; rh < 2; rh++) {
#pragma unroll
        for (int i = 0; i < 4; i++) {
            const int m = m0 + rh * 64 + ty * 4 + i;
            const float gm = (float)gate[m];
#pragma unroll
            for (int ch = 0; ch < 2; ch++) {
                const int n = n0 + ch * 64 + tx * 4;
                float4 bb = *(const float4*)(bias + n);
                float v0 = acc[rh * 4 + i][ch * 4 + 0] + bb.x;
                float v1 = acc[rh * 4 + i][ch * 4 + 1] + bb.y;
                float v2 = acc[rh * 4 + i][ch * 4 + 2] + bb.z;
                float v3 = acc[rh * 4 + i][ch * 4 + 3] + bb.w;
                float4 o;
                if (MODE != 3) {
                    o.x = v0 * gm; o.y = v1 * gm; o.z = v2 * gm; o.w = v3 * gm;
                } else {
                    float4 xr = *(const float4*)(X + (size_t)m * DM + n);
                    const float og = 1.f - gm;
                    o.x = xr.x * og + v0 * gm;
                    o.y = xr.y * og + v1 * gm;
                    o.z = xr.z * og + v2 * gm;
                    o.w = xr.w * og + v3 * gm;
                }
                *(float4*)(C + (size_t)m * DM + n) = o;
            }
        }
    }
}

// ---------------------------------------------------------------------------
// Flash attention, fp32. One CTA = 64 query rows of one (b, h).
// Thread t: row r = t/4, dim-chunk c = t%4 (dims 16c..16c+15).
// Online softmax in 16-key chunks; K/V tiles (64x64) staged via smem.
// ---------------------------------------------------------------------------
__global__ __launch_bounds__(256) void attn_k()
{
    __shared__ float Ks[64][64];
    __shared__ float Vs[64][64];

    const int qt = blockIdx.x;   // query tile (0..31)
    const int h  = blockIdx.y;
    const int b  = blockIdx.z;
    const int tid = threadIdx.x;
    const int r = tid >> 2;
    const int c = tid & 3;
    const int m0 = b * S_ + qt * 64;
    const int dcol = h * HD;

    // q pre-scaled by 1/sqrt(64)
    float q[16];
    {
        const float4* qp =
            (const float4*)(g_q + (size_t)(m0 + r) * DM + dcol + c * 16);
#pragma unroll
        for (int i = 0; i < 4; i++) {
            float4 t = qp[i];
            q[i * 4 + 0] = t.x * 0.125f;
            q[i * 4 + 1] = t.y * 0.125f;
            q[i * 4 + 2] = t.z * 0.125f;
            q[i * 4 + 3] = t.w * 0.125f;
        }
    }

    float o[16];
#pragma unroll
    for (int i = 0; i < 16; i++) o[i] = 0.f;
    float mi = -1e30f, l = 0.f;

    const int lrow = tid >> 2;
    const int lcol = (tid & 3) * 16;

    for (int kt = 0; kt < S_ / 64; kt++) {
        const size_t gro = (size_t)(b * S_ + kt * 64 + lrow) * DM + dcol + lcol;
        float4 kv[4], vv[4];
#pragma unroll
        for (int i = 0; i < 4; i++) {
            kv[i] = *(const float4*)(g_k + gro + i * 4);
            vv[i] = *(const float4*)(g_v + gro + i * 4);
        }
        __syncthreads();
#pragma unroll
        for (int i = 0; i < 4; i++) {
            *(float4*)&Ks[lrow][lcol + i * 4] = kv[i];
            *(float4*)&Vs[lrow][lcol + i * 4] = vv[i];
        }
        __syncthreads();

#pragma unroll
        for (int chunk = 0; chunk < 4; chunk++) {
            float s[16];
#pragma unroll
            for (int j = 0; j < 16; j++) {
                const float4* kp = (const float4*)&Ks[chunk * 16 + j][c * 16];
                float a = 0.f;
#pragma unroll
                for (int i = 0; i < 4; i++) {
                    float4 kk = kp[i];
                    a = fmaf(q[i * 4 + 0], kk.x, a);
                    a = fmaf(q[i * 4 + 1], kk.y, a);
                    a = fmaf(q[i * 4 + 2], kk.z, a);
                    a = fmaf(q[i * 4 + 3], kk.w, a);
                }
                a += __shfl_xor_sync(0xffffffffu, a, 1);
                a += __shfl_xor_sync(0xffffffffu, a, 2);
                s[j] = a;
            }
            float cmax = s[0];
#pragma unroll
            for (int j = 1; j < 16; j++) cmax = fmaxf(cmax, s[j]);
            const float mnew = fmaxf(mi, cmax);
            const float corr = __expf(mi - mnew);
            l *= corr;
#pragma unroll
            for (int i = 0; i < 16; i++) o[i] *= corr;
            mi = mnew;
#pragma unroll
            for (int j = 0; j < 16; j++) {
                const float p = __expf(s[j] - mnew);
                l += p;
                const float4* vp = (const float4*)&Vs[chunk * 16 + j][c * 16];
#pragma unroll
                for (int i = 0; i < 4; i++) {
                    float4 vx = vp[i];
                    o[i * 4 + 0] = fmaf(p, vx.x, o[i * 4 + 0]);
                    o[i * 4 + 1] = fmaf(p, vx.y, o[i * 4 + 1]);
                    o[i * 4 + 2] = fmaf(p, vx.z, o[i * 4 + 2]);
                    o[i * 4 + 3] = fmaf(p, vx.w, o[i * 4 + 3]);
                }
            }
        }
    }

    const float inv = 1.f / l;
    float* op = g_ctx + (size_t)(m0 + r) * DM + dcol + c * 16;
#pragma unroll
    for (int i = 0; i < 4; i++) {
        float4 t;
        t.x = o[i * 4 + 0] * inv;
        t.y = o[i * 4 + 1] * inv;
        t.z = o[i * 4 + 2] * inv;
        t.w = o[i * 4 + 3] * inv;
        *(float4*)(op + i * 4) = t;
    }
}

// ---------------------------------------------------------------------------
extern "C" void kernel_launch(void* const* d_in, const int* in_sizes, int n_in,
                              void* d_out, int out_size)
{
    const float* x    = (const float*)d_in[0];
    const int*   gate = (const int*)  d_in[1];
    const float* Wq   = (const float*)d_in[2];
    const float* bq   = (const float*)d_in[3];
    const float* Wk   = (const float*)d_in[4];
    const float* bk   = (const float*)d_in[5];
    const float* Wv   = (const float*)d_in[6];
    const float* bv   = (const float*)d_in[7];
    const float* Wo   = (const float*)d_in[8];
    const float* bo   = (const float*)d_in[9];
    float* out = (float*)d_out;

    dim3 gg(DM / 128, MTOT / 128);   // (8, 32)
    sgemm_k<0><<<gg, 256>>>(x, Wq, bq, gate, nullptr);
    sgemm_k<1><<<gg, 256>>>(x, Wk, bk, gate, nullptr);
    sgemm_k<2><<<gg, 256>>>(x, Wv, bv, gate, nullptr);
    attn_k<<<dim3(S_ / 64, HEADS, B_), 256>>>();
    sgemm_k<3><<<gg, 256>>>(x, Wo, bo, gate, out);
}

// round 4
// speedup vs baseline: 1.7184x; 1.7184x over previous
#include <cuda_runtime.h>
#include <cuda_bf16.h>
#include <cstdint>
#include <cstddef>

#define DM 1024
#define HEADS 16
#define HD 64
#define B_ 2
#define S_ 2048
#define MTOT 4096   // B*S

// ---------------------------------------------------------------------------
// Scratch (__device__ globals; allocation-free rule)
// ---------------------------------------------------------------------------
__device__ float g_q[MTOT * DM];
__device__ float g_k[MTOT * DM];
__device__ float g_v[MTOT * DM];
__device__ float g_ctx[MTOT * DM];
__device__ __nv_bfloat16 g_xh[MTOT * DM];
__device__ __nv_bfloat16 g_xl[MTOT * DM];
__device__ __nv_bfloat16 g_ch[MTOT * DM];
__device__ __nv_bfloat16 g_cl[MTOT * DM];
__device__ __nv_bfloat16 g_wh[4][DM * DM];   // W^T hi, [n][k]
__device__ __nv_bfloat16 g_wl[4][DM * DM];   // W^T lo, [n][k]

// ---------------------------------------------------------------------------
// sm_100-safe PTX helpers (mma.sync / ldmatrix / cp.async only)
// ---------------------------------------------------------------------------
__device__ __forceinline__ uint32_t smem_u32(const void* p) {
    uint32_t a;
    asm("{ .reg .u64 t; cvta.to.shared.u64 t, %1; cvt.u32.u64 %0, t; }"
        : "=r"(a) : "l"(p));
    return a;
}
__device__ __forceinline__ void ldsm_x4(uint32_t* r, uint32_t addr) {
    asm volatile("ldmatrix.sync.aligned.m8n8.x4.shared.b16 {%0,%1,%2,%3}, [%4];"
                 : "=r"(r[0]), "=r"(r[1]), "=r"(r[2]), "=r"(r[3]) : "r"(addr));
}
__device__ __forceinline__ void mma_bf16(float* d, const uint32_t* a, const uint32_t* b) {
    asm volatile(
        "mma.sync.aligned.m16n8k16.row.col.f32.bf16.bf16.f32 "
        "{%0,%1,%2,%3},{%4,%5,%6,%7},{%8,%9},{%0,%1,%2,%3};"
        : "+f"(d[0]), "+f"(d[1]), "+f"(d[2]), "+f"(d[3])
        : "r"(a[0]), "r"(a[1]), "r"(a[2]), "r"(a[3]), "r"(b[0]), "r"(b[1]));
}
__device__ __forceinline__ void cp16(uint32_t s, const void* g) {
    asm volatile("cp.async.cg.shared.global [%0], [%1], 16;" :: "r"(s), "l"(g));
}
#define CP_COMMIT() asm volatile("cp.async.commit_group;" ::: "memory")
#define CP_WAIT0()  asm volatile("cp.async.wait_group 0;" ::: "memory")

// ---------------------------------------------------------------------------
// fp32 -> bf16 hi/lo split conversion
// ---------------------------------------------------------------------------
template <bool CTX>
__global__ void conv_split(const float* __restrict__ src)
{
    const int i = (blockIdx.x * blockDim.x + threadIdx.x) * 4;
    const float* s = CTX ? (const float*)g_ctx : src;
    __nv_bfloat16* ph = CTX ? g_ch : g_xh;
    __nv_bfloat16* pl = CTX ? g_cl : g_xl;
    float4 v = *(const float4*)(s + i);
    __nv_bfloat16 h0 = __float2bfloat16(v.x);
    __nv_bfloat16 h1 = __float2bfloat16(v.y);
    __nv_bfloat16 h2 = __float2bfloat16(v.z);
    __nv_bfloat16 h3 = __float2bfloat16(v.w);
    __nv_bfloat16 l0 = __float2bfloat16(v.x - __bfloat162float(h0));
    __nv_bfloat16 l1 = __float2bfloat16(v.y - __bfloat162float(h1));
    __nv_bfloat16 l2 = __float2bfloat16(v.z - __bfloat162float(h2));
    __nv_bfloat16 l3 = __float2bfloat16(v.w - __bfloat162float(h3));
    *(__nv_bfloat162*)(ph + i)     = __nv_bfloat162(h0, h1);
    *(__nv_bfloat162*)(ph + i + 2) = __nv_bfloat162(h2, h3);
    *(__nv_bfloat162*)(pl + i)     = __nv_bfloat162(l0, l1);
    *(__nv_bfloat162*)(pl + i + 2) = __nv_bfloat162(l2, l3);
}

// ---------------------------------------------------------------------------
// W [K][N] fp32 -> transposed bf16 hi/lo splits g_wh/g_wl[widx] as [n][k]
// ---------------------------------------------------------------------------
__global__ void conv_w(const float* __restrict__ W, int widx)
{
    __shared__ float t[32][33];
    const int k0 = blockIdx.y * 32, n0 = blockIdx.x * 32;
    const int tx = threadIdx.x, ty = threadIdx.y;
#pragma unroll
    for (int i = 0; i < 4; i++)
        t[ty + i * 8][tx] = W[(size_t)(k0 + ty + i * 8) * DM + n0 + tx];
    __syncthreads();
    __nv_bfloat16* ph = g_wh[widx];
    __nv_bfloat16* pl = g_wl[widx];
#pragma unroll
    for (int i = 0; i < 4; i++) {
        float v = t[tx][ty + i * 8];
        __nv_bfloat16 hh = __float2bfloat16(v);
        __nv_bfloat16 ll = __float2bfloat16(v - __bfloat162float(hh));
        ph[(size_t)(n0 + ty + i * 8) * DM + k0 + tx] = hh;
        pl[(size_t)(n0 + ty + i * 8) * DM + k0 + tx] = ll;
    }
}

// ---------------------------------------------------------------------------
// Split-bf16 HMMA GEMM: C = A @ W + bias (+epilogue)
// A hi/lo [M][K] K-major; B = W^T hi/lo [N][K] K-major.
// CTA 128x128, BK=32, 8 warps (2x4), warp tile 64x32, m16n8k16.
// 3-pass split: Ah*Bh + Ah*Bl + Al*Bh.
// Smem: per stage 4 tiles of [128][40] bf16 (80B row stride: ldmatrix
// conflict-free since 80*r mod 128 covers all 8 16B banks). 2 stages.
// ---------------------------------------------------------------------------
#define TILE_B 10240                      // 128*40*2 bytes
#define STAGE_B (4 * TILE_B)              // 40960
#define GSMEM_TOT (2 * STAGE_B)           // 81920

template <int MODE>
__global__ __launch_bounds__(256, 1) void gemm_mma(
    int widx, const float* __restrict__ bias, const int* __restrict__ gate,
    const float* __restrict__ X, float* __restrict__ Cout)
{
    extern __shared__ char smem[];
    const uint32_t sb = smem_u32(smem);
    const int tid = threadIdx.x;
    const int wid = tid >> 5;
    const int lane = tid & 31;
    const int wm = wid >> 2;       // 0..1
    const int wn = wid & 3;        // 0..3
    const int m0 = blockIdx.y * 128, n0 = blockIdx.x * 128;

    const __nv_bfloat16* Ah = (MODE == 3) ? g_ch : g_xh;
    const __nv_bfloat16* Al = (MODE == 3) ? g_cl : g_xl;
    const __nv_bfloat16* Bh = g_wh[widx];
    const __nv_bfloat16* Bl = g_wl[widx];
    float* C;
    if (MODE == 0)      C = g_q;
    else if (MODE == 1) C = g_k;
    else if (MODE == 2) C = g_v;
    else                C = Cout;

    float acc[4][4][4];
#pragma unroll
    for (int i = 0; i < 4; i++)
#pragma unroll
        for (int j = 0; j < 4; j++)
#pragma unroll
            for (int e = 0; e < 4; e++) acc[i][j][e] = 0.f;

    // loader indices: each thread: row=tid>>1, chunks (tid&1)*2, +1 per tile
    const int lrow = tid >> 1;
    const int lc0 = (tid & 1) * 2;

    auto load_stage = [&](int st, int kc) {
        const int k0 = kc * 32;
        const uint32_t sbase = sb + st * STAGE_B;
        const size_t goA = (size_t)(m0 + lrow) * DM + k0;
        const size_t goB = (size_t)(n0 + lrow) * DM + k0;
#pragma unroll
        for (int c = 0; c < 2; c++) {
            const int ch = lc0 + c;                 // 16B chunk 0..3
            const uint32_t so = lrow * 80 + ch * 16;
            cp16(sbase + so,              Ah + goA + ch * 8);
            cp16(sbase + TILE_B + so,     Al + goA + ch * 8);
            cp16(sbase + 2 * TILE_B + so, Bh + goB + ch * 8);
            cp16(sbase + 3 * TILE_B + so, Bl + goB + ch * 8);
        }
    };

    // ldmatrix lane addressing
    const int aRowOff = lane & 15;                 // + (lane>>4)*8 cols
    const int aColB0 = ((lane >> 4) << 3) * 2;     // bytes (k half)
    const int bRowOff = (lane & 7) + ((lane >> 4) << 3);
    const int bColB0 = (((lane >> 3) & 1) << 3) * 2;

    load_stage(0, 0);
    CP_COMMIT();
    CP_WAIT0();
    __syncthreads();

    const int NCH = DM / 32;   // 32
    for (int kc = 0; kc < NCH; kc++) {
        const int cur = kc & 1;
        if (kc + 1 < NCH) { load_stage(1 - cur, kc + 1); CP_COMMIT(); }

        const uint32_t stb = sb + cur * STAGE_B;
#pragma unroll
        for (int ks = 0; ks < 2; ks++) {
            uint32_t ah[4][4], al[4][4], bh[4][2], bl[4][2];
            const int kB = ks * 32;   // 16 bf16 = 32 bytes
#pragma unroll
            for (int mf = 0; mf < 4; mf++) {
                const uint32_t ra = (wm * 64 + mf * 16 + aRowOff) * 80 + kB + aColB0;
                ldsm_x4(ah[mf], stb + ra);
                ldsm_x4(al[mf], stb + TILE_B + ra);
            }
#pragma unroll
            for (int np = 0; np < 2; np++) {
                const uint32_t rb = (wn * 32 + np * 16 + bRowOff) * 80 + kB + bColB0;
                uint32_t t[4];
                ldsm_x4(t, stb + 2 * TILE_B + rb);
                bh[np * 2][0] = t[0]; bh[np * 2][1] = t[1];
                bh[np * 2 + 1][0] = t[2]; bh[np * 2 + 1][1] = t[3];
                ldsm_x4(t, stb + 3 * TILE_B + rb);
                bl[np * 2][0] = t[0]; bl[np * 2][1] = t[1];
                bl[np * 2 + 1][0] = t[2]; bl[np * 2 + 1][1] = t[3];
            }
#pragma unroll
            for (int mf = 0; mf < 4; mf++)
#pragma unroll
                for (int nf = 0; nf < 4; nf++) {
                    mma_bf16(acc[mf][nf], ah[mf], bh[nf]);
                    mma_bf16(acc[mf][nf], ah[mf], bl[nf]);
                    mma_bf16(acc[mf][nf], al[mf], bh[nf]);
                }
        }
        if (kc + 1 < NCH) { CP_WAIT0(); __syncthreads(); }
    }

    // epilogue: c0,c1 at (row, col..col+1); c2,c3 at (row+8, ...)
#pragma unroll
    for (int mf = 0; mf < 4; mf++) {
        const int row = m0 + wm * 64 + mf * 16 + (lane >> 2);
#pragma unroll
        for (int half = 0; half < 2; half++) {
            const int r = row + half * 8;
            const float gm = (float)gate[r];
            const float og = 1.f - gm;
#pragma unroll
            for (int nf = 0; nf < 4; nf++) {
                const int col = n0 + wn * 32 + nf * 8 + ((lane & 3) << 1);
                float v0 = acc[mf][nf][half * 2 + 0] + bias[col];
                float v1 = acc[mf][nf][half * 2 + 1] + bias[col + 1];
                float2 o;
                if (MODE != 3) {
                    o.x = v0 * gm; o.y = v1 * gm;
                } else {
                    const float2 xr = *(const float2*)(X + (size_t)r * DM + col);
                    o.x = xr.x * og + v0 * gm;
                    o.y = xr.y * og + v1 * gm;
                }
                *(float2*)(C + (size_t)r * DM + col) = o;
            }
        }
    }
}

// ---------------------------------------------------------------------------
// Flash attention, fp32. CTA = 128 query rows of one (b, h); thread owns
// rows r and r+64, dim-chunk c (16 dims). 2-row blocking halves LDS traffic.
// ---------------------------------------------------------------------------
__global__ __launch_bounds__(256) void attn_k()
{
    __shared__ float Ks[64][68];
    __shared__ float Vs[64][68];

    const int qt = blockIdx.x;
    const int h  = blockIdx.y;
    const int b  = blockIdx.z;
    const int tid = threadIdx.x;
    const int r = tid >> 2;
    const int c = tid & 3;
    const int m0 = b * S_ + qt * 128;
    const int dcol = h * HD;

    float q0[16], q1[16];
    {
        const float4* qa = (const float4*)(g_q + (size_t)(m0 + r) * DM + dcol + c * 16);
        const float4* qb = (const float4*)(g_q + (size_t)(m0 + r + 64) * DM + dcol + c * 16);
#pragma unroll
        for (int i = 0; i < 4; i++) {
            float4 t = qa[i];
            q0[i * 4 + 0] = t.x * 0.125f; q0[i * 4 + 1] = t.y * 0.125f;
            q0[i * 4 + 2] = t.z * 0.125f; q0[i * 4 + 3] = t.w * 0.125f;
            float4 u = qb[i];
            q1[i * 4 + 0] = u.x * 0.125f; q1[i * 4 + 1] = u.y * 0.125f;
            q1[i * 4 + 2] = u.z * 0.125f; q1[i * 4 + 3] = u.w * 0.125f;
        }
    }

    float o0[16], o1[16];
#pragma unroll
    for (int i = 0; i < 16; i++) { o0[i] = 0.f; o1[i] = 0.f; }
    float mi0 = -1e30f, mi1 = -1e30f, l0 = 0.f, l1 = 0.f;

    for (int kt = 0; kt < S_ / 64; kt++) {
        const size_t gro = (size_t)(b * S_ + kt * 64 + r) * DM + dcol + c * 16;
        float4 kv[4], vv[4];
#pragma unroll
        for (int i = 0; i < 4; i++) {
            kv[i] = *(const float4*)(g_k + gro + i * 4);
            vv[i] = *(const float4*)(g_v + gro + i * 4);
        }
        __syncthreads();
#pragma unroll
        for (int i = 0; i < 4; i++) {
            *(float4*)&Ks[r][c * 16 + i * 4] = kv[i];
            *(float4*)&Vs[r][c * 16 + i * 4] = vv[i];
        }
        __syncthreads();

#pragma unroll
        for (int chunk = 0; chunk < 4; chunk++) {
            float s0[16], s1[16];
#pragma unroll
            for (int j = 0; j < 16; j++) {
                const float4* kp = (const float4*)&Ks[chunk * 16 + j][c * 16];
                float a0 = 0.f, a1 = 0.f;
#pragma unroll
                for (int i = 0; i < 4; i++) {
                    float4 kk = kp[i];
                    a0 = fmaf(q0[i * 4 + 0], kk.x, a0);
                    a0 = fmaf(q0[i * 4 + 1], kk.y, a0);
                    a0 = fmaf(q0[i * 4 + 2], kk.z, a0);
                    a0 = fmaf(q0[i * 4 + 3], kk.w, a0);
                    a1 = fmaf(q1[i * 4 + 0], kk.x, a1);
                    a1 = fmaf(q1[i * 4 + 1], kk.y, a1);
                    a1 = fmaf(q1[i * 4 + 2], kk.z, a1);
                    a1 = fmaf(q1[i * 4 + 3], kk.w, a1);
                }
                a0 += __shfl_xor_sync(0xffffffffu, a0, 1);
                a0 += __shfl_xor_sync(0xffffffffu, a0, 2);
                a1 += __shfl_xor_sync(0xffffffffu, a1, 1);
                a1 += __shfl_xor_sync(0xffffffffu, a1, 2);
                s0[j] = a0; s1[j] = a1;
            }
            float cm0 = s0[0], cm1 = s1[0];
#pragma unroll
            for (int j = 1; j < 16; j++) {
                cm0 = fmaxf(cm0, s0[j]);
                cm1 = fmaxf(cm1, s1[j]);
            }
            const float mn0 = fmaxf(mi0, cm0);
            const float mn1 = fmaxf(mi1, cm1);
            const float cr0 = __expf(mi0 - mn0);
            const float cr1 = __expf(mi1 - mn1);
            l0 *= cr0; l1 *= cr1;
#pragma unroll
            for (int i = 0; i < 16; i++) { o0[i] *= cr0; o1[i] *= cr1; }
            mi0 = mn0; mi1 = mn1;
#pragma unroll
            for (int j = 0; j < 16; j++) {
                const float p0 = __expf(s0[j] - mi0);
                const float p1 = __expf(s1[j] - mi1);
                l0 += p0; l1 += p1;
                const float4* vp = (const float4*)&Vs[chunk * 16 + j][c * 16];
#pragma unroll
                for (int i = 0; i < 4; i++) {
                    float4 vx = vp[i];
                    o0[i * 4 + 0] = fmaf(p0, vx.x, o0[i * 4 + 0]);
                    o0[i * 4 + 1] = fmaf(p0, vx.y, o0[i * 4 + 1]);
                    o0[i * 4 + 2] = fmaf(p0, vx.z, o0[i * 4 + 2]);
                    o0[i * 4 + 3] = fmaf(p0, vx.w, o0[i * 4 + 3]);
                    o1[i * 4 + 0] = fmaf(p1, vx.x, o1[i * 4 + 0]);
                    o1[i * 4 + 1] = fmaf(p1, vx.y, o1[i * 4 + 1]);
                    o1[i * 4 + 2] = fmaf(p1, vx.z, o1[i * 4 + 2]);
                    o1[i * 4 + 3] = fmaf(p1, vx.w, o1[i * 4 + 3]);
                }
            }
        }
    }

    const float inv0 = 1.f / l0;
    const float inv1 = 1.f / l1;
    float* opa = g_ctx + (size_t)(m0 + r) * DM + dcol + c * 16;
    float* opb = g_ctx + (size_t)(m0 + r + 64) * DM + dcol + c * 16;
#pragma unroll
    for (int i = 0; i < 4; i++) {
        float4 ta, tb;
        ta.x = o0[i * 4 + 0] * inv0; ta.y = o0[i * 4 + 1] * inv0;
        ta.z = o0[i * 4 + 2] * inv0; ta.w = o0[i * 4 + 3] * inv0;
        tb.x = o1[i * 4 + 0] * inv1; tb.y = o1[i * 4 + 1] * inv1;
        tb.z = o1[i * 4 + 2] * inv1; tb.w = o1[i * 4 + 3] * inv1;
        *(float4*)(opa + i * 4) = ta;
        *(float4*)(opb + i * 4) = tb;
    }
}

// ---------------------------------------------------------------------------
extern "C" void kernel_launch(void* const* d_in, const int* in_sizes, int n_in,
                              void* d_out, int out_size)
{
    const float* x    = (const float*)d_in[0];
    const int*   gate = (const int*)  d_in[1];
    const float* Wq   = (const float*)d_in[2];
    const float* bq   = (const float*)d_in[3];
    const float* Wk   = (const float*)d_in[4];
    const float* bk   = (const float*)d_in[5];
    const float* Wv   = (const float*)d_in[6];
    const float* bv   = (const float*)d_in[7];
    const float* Wo   = (const float*)d_in[8];
    const float* bo   = (const float*)d_in[9];
    float* out = (float*)d_out;

    cudaFuncSetAttribute(gemm_mma<0>, cudaFuncAttributeMaxDynamicSharedMemorySize, GSMEM_TOT);
    cudaFuncSetAttribute(gemm_mma<1>, cudaFuncAttributeMaxDynamicSharedMemorySize, GSMEM_TOT);
    cudaFuncSetAttribute(gemm_mma<2>, cudaFuncAttributeMaxDynamicSharedMemorySize, GSMEM_TOT);
    cudaFuncSetAttribute(gemm_mma<3>, cudaFuncAttributeMaxDynamicSharedMemorySize, GSMEM_TOT);

    conv_split<false><<<MTOT * DM / 1024, 256>>>(x);
    conv_w<<<dim3(32, 32), dim3(32, 8)>>>(Wq, 0);
    conv_w<<<dim3(32, 32), dim3(32, 8)>>>(Wk, 1);
    conv_w<<<dim3(32, 32), dim3(32, 8)>>>(Wv, 2);
    conv_w<<<dim3(32, 32), dim3(32, 8)>>>(Wo, 3);

    dim3 gg(DM / 128, MTOT / 128);   // (8, 32)
    gemm_mma<0><<<gg, 256, GSMEM_TOT>>>(0, bq, gate, x, nullptr);
    gemm_mma<1><<<gg, 256, GSMEM_TOT>>>(1, bk, gate, x, nullptr);
    gemm_mma<2><<<gg, 256, GSMEM_TOT>>>(2, bv, gate, x, nullptr);

    attn_k<<<dim3(S_ / 128, HEADS, B_), 256>>>();

    conv_split<true><<<MTOT * DM / 1024, 256>>>(nullptr);
    gemm_mma<3><<<gg, 256, GSMEM_TOT>>>(3, bo, gate, x, out);
}

// round 6
// speedup vs baseline: 6.2894x; 3.6600x over previous
#include <cuda_runtime.h>
#include <cuda_bf16.h>
#include <cstdint>
#include <cstddef>
#include <cstring>

#define DM 1024
#define HEADS 16
#define HD 64
#define B_ 2
#define S_ 2048
#define MTOT 4096   // B*S

// ---------------------------------------------------------------------------
// Scratch (__device__ globals; allocation-free rule). All split-bf16.
// ---------------------------------------------------------------------------
__device__ __nv_bfloat16 g_xh[MTOT * DM];
__device__ __nv_bfloat16 g_xl[MTOT * DM];
__device__ __nv_bfloat16 g_qh[MTOT * DM];   // pre-scaled by 1/8
__device__ __nv_bfloat16 g_ql[MTOT * DM];
__device__ __nv_bfloat16 g_kh[MTOT * DM];
__device__ __nv_bfloat16 g_kl[MTOT * DM];
__device__ __nv_bfloat16 g_vh[MTOT * DM];
__device__ __nv_bfloat16 g_vl[MTOT * DM];
__device__ __nv_bfloat16 g_ch[MTOT * DM];   // attention context
__device__ __nv_bfloat16 g_cl[MTOT * DM];
__device__ __nv_bfloat16 g_wh[4][DM * DM];  // W^T hi, [n][k]
__device__ __nv_bfloat16 g_wl[4][DM * DM];  // W^T lo, [n][k]

// ---------------------------------------------------------------------------
// sm_100-safe PTX helpers
// ---------------------------------------------------------------------------
__device__ __forceinline__ uint32_t smem_u32(const void* p) {
    uint32_t a;
    asm("{ .reg .u64 t; cvta.to.shared.u64 t, %1; cvt.u32.u64 %0, t; }"
        : "=r"(a) : "l"(p));
    return a;
}
__device__ __forceinline__ void ldsm_x4(uint32_t* r, uint32_t addr) {
    asm volatile("ldmatrix.sync.aligned.m8n8.x4.shared.b16 {%0,%1,%2,%3}, [%4];"
                 : "=r"(r[0]), "=r"(r[1]), "=r"(r[2]), "=r"(r[3]) : "r"(addr));
}
__device__ __forceinline__ void ldsm_x4t(uint32_t* r, uint32_t addr) {
    asm volatile("ldmatrix.sync.aligned.m8n8.x4.trans.shared.b16 {%0,%1,%2,%3}, [%4];"
                 : "=r"(r[0]), "=r"(r[1]), "=r"(r[2]), "=r"(r[3]) : "r"(addr));
}
__device__ __forceinline__ void mma_bf16(float* d, const uint32_t* a, const uint32_t* b) {
    asm volatile(
        "mma.sync.aligned.m16n8k16.row.col.f32.bf16.bf16.f32 "
        "{%0,%1,%2,%3},{%4,%5,%6,%7},{%8,%9},{%0,%1,%2,%3};"
        : "+f"(d[0]), "+f"(d[1]), "+f"(d[2]), "+f"(d[3])
        : "r"(a[0]), "r"(a[1]), "r"(a[2]), "r"(a[3]), "r"(b[0]), "r"(b[1]));
}
__device__ __forceinline__ void cp16(uint32_t s, const void* g) {
    asm volatile("cp.async.cg.shared.global [%0], [%1], 16;" :: "r"(s), "l"(g));
}
#define CP_COMMIT() asm volatile("cp.async.commit_group;" ::: "memory")
#define CP_WAIT0()  asm volatile("cp.async.wait_group 0;" ::: "memory")
#define CP_WAIT1()  asm volatile("cp.async.wait_group 1;" ::: "memory")

__device__ __forceinline__ uint32_t pack2bf(float lo, float hi) {
    uint32_t r;
    asm("cvt.rn.bf16x2.f32 %0, %1, %2;" : "=r"(r) : "f"(hi), "f"(lo));
    return r;
}
__device__ __forceinline__ void split_store(__nv_bfloat16* ph, __nv_bfloat16* pl,
                                            size_t off, float v0, float v1) {
    __nv_bfloat16 h0 = __float2bfloat16(v0);
    __nv_bfloat16 h1 = __float2bfloat16(v1);
    __nv_bfloat16 l0 = __float2bfloat16(v0 - __bfloat162float(h0));
    __nv_bfloat16 l1 = __float2bfloat16(v1 - __bfloat162float(h1));
    *(__nv_bfloat162*)(ph + off) = __nv_bfloat162(h0, h1);
    *(__nv_bfloat162*)(pl + off) = __nv_bfloat162(l0, l1);
}

// ---------------------------------------------------------------------------
// fp32 x -> bf16 hi/lo split
// ---------------------------------------------------------------------------
__global__ void conv_split(const float* __restrict__ src)
{
    const int i = (blockIdx.x * blockDim.x + threadIdx.x) * 4;
    float4 v = *(const float4*)(src + i);
    split_store(g_xh, g_xl, i, v.x, v.y);
    split_store(g_xh, g_xl, i + 2, v.z, v.w);
}

// ---------------------------------------------------------------------------
// W [K][N] fp32 -> transposed bf16 hi/lo splits g_wh/g_wl[widx] as [n][k]
// ---------------------------------------------------------------------------
__global__ void conv_w(const float* __restrict__ W, int widx)
{
    __shared__ float t[32][33];
    const int k0 = blockIdx.y * 32, n0 = blockIdx.x * 32;
    const int tx = threadIdx.x, ty = threadIdx.y;
#pragma unroll
    for (int i = 0; i < 4; i++)
        t[ty + i * 8][tx] = W[(size_t)(k0 + ty + i * 8) * DM + n0 + tx];
    __syncthreads();
    __nv_bfloat16* ph = g_wh[widx];
    __nv_bfloat16* pl = g_wl[widx];
#pragma unroll
    for (int i = 0; i < 4; i++) {
        float v = t[tx][ty + i * 8];
        __nv_bfloat16 hh = __float2bfloat16(v);
        __nv_bfloat16 ll = __float2bfloat16(v - __bfloat162float(hh));
        ph[(size_t)(n0 + ty + i * 8) * DM + k0 + tx] = hh;
        pl[(size_t)(n0 + ty + i * 8) * DM + k0 + tx] = ll;
    }
}

// ---------------------------------------------------------------------------
// Split-bf16 HMMA GEMM (validated R4 core).
// MODE 0: fused QKV (blockIdx.z = 0/1/2 -> q/k/v split outputs, gated, Q/8)
// MODE 3: O proj: A = ctx split, out = x*(1-g) + (A@Wo + bo)*g  (fp32)
// ---------------------------------------------------------------------------
#define TILE_B 10240                      // 128*40*2 bytes
#define STAGE_B (4 * TILE_B)              // 40960
#define GSMEM_TOT (2 * STAGE_B)           // 81920

template <int MODE>
__global__ __launch_bounds__(256, 1) void gemm_mma(
    const float* __restrict__ bias0, const float* __restrict__ bias1,
    const float* __restrict__ bias2, const int* __restrict__ gate,
    const float* __restrict__ X, float* __restrict__ Cout)
{
    extern __shared__ char smem[];
    const uint32_t sb = smem_u32(smem);
    const int tid = threadIdx.x;
    const int wid = tid >> 5;
    const int lane = tid & 31;
    const int wm = wid >> 2;
    const int wn = wid & 3;
    const int m0 = blockIdx.y * 128, n0 = blockIdx.x * 128;
    const int z = (MODE == 0) ? blockIdx.z : 3;

    const __nv_bfloat16* Ah = (MODE == 3) ? g_ch : g_xh;
    const __nv_bfloat16* Al = (MODE == 3) ? g_cl : g_xl;
    const __nv_bfloat16* Bh = g_wh[z];
    const __nv_bfloat16* Bl = g_wl[z];
    const float* bias = (MODE == 3) ? bias0 : (z == 0 ? bias0 : (z == 1 ? bias1 : bias2));
    __nv_bfloat16* Oh = nullptr;
    __nv_bfloat16* Ol = nullptr;
    if (MODE == 0) {
        Oh = (z == 0) ? g_qh : (z == 1) ? g_kh : g_vh;
        Ol = (z == 0) ? g_ql : (z == 1) ? g_kl : g_vl;
    }

    float acc[4][4][4];
#pragma unroll
    for (int i = 0; i < 4; i++)
#pragma unroll
        for (int j = 0; j < 4; j++)
#pragma unroll
            for (int e = 0; e < 4; e++) acc[i][j][e] = 0.f;

    const int lrow = tid >> 1;
    const int lc0 = (tid & 1) * 2;

    auto load_stage = [&](int st, int kc) {
        const int k0 = kc * 32;
        const uint32_t sbase = sb + st * STAGE_B;
        const size_t goA = (size_t)(m0 + lrow) * DM + k0;
        const size_t goB = (size_t)(n0 + lrow) * DM + k0;
#pragma unroll
        for (int c = 0; c < 2; c++) {
            const int ch = lc0 + c;
            const uint32_t so = lrow * 80 + ch * 16;
            cp16(sbase + so,              Ah + goA + ch * 8);
            cp16(sbase + TILE_B + so,     Al + goA + ch * 8);
            cp16(sbase + 2 * TILE_B + so, Bh + goB + ch * 8);
            cp16(sbase + 3 * TILE_B + so, Bl + goB + ch * 8);
        }
    };

    const int aRowOff = lane & 15;
    const int aColB0 = ((lane >> 4) << 3) * 2;
    const int bRowOff = (lane & 7) + ((lane >> 4) << 3);
    const int bColB0 = (((lane >> 3) & 1) << 3) * 2;

    load_stage(0, 0);
    CP_COMMIT();
    CP_WAIT0();
    __syncthreads();

    const int NCH = DM / 32;
    for (int kc = 0; kc < NCH; kc++) {
        const int cur = kc & 1;
        if (kc + 1 < NCH) { load_stage(1 - cur, kc + 1); CP_COMMIT(); }

        const uint32_t stb = sb + cur * STAGE_B;
#pragma unroll
        for (int ks = 0; ks < 2; ks++) {
            uint32_t ah[4][4], al[4][4], bh[4][2], bl[4][2];
            const int kB = ks * 32;
#pragma unroll
            for (int mf = 0; mf < 4; mf++) {
                const uint32_t ra = (wm * 64 + mf * 16 + aRowOff) * 80 + kB + aColB0;
                ldsm_x4(ah[mf], stb + ra);
                ldsm_x4(al[mf], stb + TILE_B + ra);
            }
#pragma unroll
            for (int np = 0; np < 2; np++) {
                const uint32_t rb = (wn * 32 + np * 16 + bRowOff) * 80 + kB + bColB0;
                uint32_t t[4];
                ldsm_x4(t, stb + 2 * TILE_B + rb);
                bh[np * 2][0] = t[0]; bh[np * 2][1] = t[1];
                bh[np * 2 + 1][0] = t[2]; bh[np * 2 + 1][1] = t[3];
                ldsm_x4(t, stb + 3 * TILE_B + rb);
                bl[np * 2][0] = t[0]; bl[np * 2][1] = t[1];
                bl[np * 2 + 1][0] = t[2]; bl[np * 2 + 1][1] = t[3];
            }
#pragma unroll
            for (int mf = 0; mf < 4; mf++)
#pragma unroll
                for (int nf = 0; nf < 4; nf++) {
                    mma_bf16(acc[mf][nf], ah[mf], bh[nf]);
                    mma_bf16(acc[mf][nf], ah[mf], bl[nf]);
                    mma_bf16(acc[mf][nf], al[mf], bh[nf]);
                }
        }
        if (kc + 1 < NCH) { CP_WAIT0(); __syncthreads(); }
    }

    const float qs = (MODE == 0 && z == 0) ? 0.125f : 1.0f;
#pragma unroll
    for (int mf = 0; mf < 4; mf++) {
        const int row = m0 + wm * 64 + mf * 16 + (lane >> 2);
#pragma unroll
        for (int half = 0; half < 2; half++) {
            const int r = row + half * 8;
            const float gm = (float)gate[r];
            const float og = 1.f - gm;
#pragma unroll
            for (int nf = 0; nf < 4; nf++) {
                const int col = n0 + wn * 32 + nf * 8 + ((lane & 3) << 1);
                float v0 = acc[mf][nf][half * 2 + 0] + bias[col];
                float v1 = acc[mf][nf][half * 2 + 1] + bias[col + 1];
                if (MODE == 0) {
                    v0 *= gm * qs; v1 *= gm * qs;
                    split_store(Oh, Ol, (size_t)r * DM + col, v0, v1);
                } else {
                    const float2 xr = *(const float2*)(X + (size_t)r * DM + col);
                    float2 o;
                    o.x = xr.x * og + v0 * gm;
                    o.y = xr.y * og + v1 * gm;
                    *(float2*)(Cout + (size_t)r * DM + col) = o;
                }
            }
        }
    }
}

// ---------------------------------------------------------------------------
// mma.sync flash attention, split-bf16 3-pass for QK^T and P.V.
// CTA: 128 query rows of one (b,h); 8 warps x 16 rows. Bc = 64 keys/iter.
// smem (bf16, pitch 72 elems = 144B):
//   Qh [0, 18432), Ql [18432, 36864)
//   stages at 36864 + st*36864: Kh +0, Kl +9216, Vh +18432, Vl +27648
// ---------------------------------------------------------------------------
#define AT_STG0  36864
#define AT_STGSZ 36864
#define AT_SMEM  (AT_STG0 + 2 * AT_STGSZ)   // 110592
#define PITCHB   144

__device__ __forceinline__ void prefetch_kv(uint32_t sb, int b, int kt, int st,
                                            int dcol, int tid)
{
    const uint32_t stg = sb + AT_STG0 + st * AT_STGSZ;
    const int gb = b * S_ + kt * 64;
#pragma unroll
    for (int t = 0; t < 8; t++) {
        const __nv_bfloat16* src =
            (t < 2) ? g_kh : (t < 4) ? g_kl : (t < 6) ? g_vh : g_vl;
        const int arr = t >> 1;
        const int rem = (tid + t * 256) - arr * 512;   // 0..511
        const int row = rem >> 3, ch = rem & 7;
        cp16(stg + arr * 9216 + row * PITCHB + ch * 16,
             src + (size_t)(gb + row) * DM + dcol + ch * 8);
    }
}

__global__ __launch_bounds__(256, 1) void attn_mma()
{
    extern __shared__ char smem[];
    const uint32_t sb = smem_u32(smem);
    const int tid = threadIdx.x, wid = tid >> 5, lane = tid & 31;
    const int qt = blockIdx.x, h = blockIdx.y, b = blockIdx.z;
    const int m0 = b * S_ + qt * 128;
    const int dcol = h * HD;

    // issue Q tile (both splits) + stage 0 K/V
#pragma unroll
    for (int t = 0; t < 8; t++) {
        const __nv_bfloat16* src = (t < 4) ? g_qh : g_ql;
        const int arr = t >> 2;
        const int rem = (tid + t * 256) - arr * 1024;  // 0..1023
        const int row = rem >> 3, ch = rem & 7;
        cp16(sb + arr * 18432 + row * PITCHB + ch * 16,
             src + (size_t)(m0 + row) * DM + dcol + ch * 8);
    }
    prefetch_kv(sb, b, 0, 0, dcol, tid);
    CP_COMMIT();
    CP_WAIT0();
    __syncthreads();

    // Q A-fragments (held in regs for the whole loop)
    uint32_t ah[4][4], al[4][4];
    {
        const int aRow = lane & 15;
        const int aCol = (lane >> 4) * 16;
#pragma unroll
        for (int kk = 0; kk < 4; kk++) {
            const uint32_t ra = (wid * 16 + aRow) * PITCHB + kk * 32 + aCol;
            ldsm_x4(ah[kk], sb + ra);
            ldsm_x4(al[kk], sb + 18432 + ra);
        }
    }

    float Oc[8][4];
#pragma unroll
    for (int j = 0; j < 8; j++)
#pragma unroll
        for (int e = 0; e < 4; e++) Oc[j][e] = 0.f;
    float mr0 = -1e30f, mr1 = -1e30f, lr0 = 0.f, lr1 = 0.f;

    const int bRowK = (lane & 7) + ((lane >> 4) << 3);
    const int bColK = ((lane >> 3) & 1) * 16;
    const int vRow = (lane & 7) + (((lane >> 3) & 1) << 3);
    const int vColB = ((lane >> 4) << 3) * 2;

    for (int kt = 0; kt < 32; kt++) {
        if (kt + 1 < 32) {
            prefetch_kv(sb, b, kt + 1, (kt + 1) & 1, dcol, tid);
            CP_COMMIT();
            CP_WAIT1();
        } else {
            CP_WAIT0();
        }
        __syncthreads();
        const uint32_t stg = sb + AT_STG0 + (kt & 1) * AT_STGSZ;

        // ---- S = Q K^T (scores pre-scaled via Q) ----
        float sacc[8][4];
#pragma unroll
        for (int j = 0; j < 8; j++)
#pragma unroll
            for (int e = 0; e < 4; e++) sacc[j][e] = 0.f;

#pragma unroll
        for (int kg = 0; kg < 4; kg++) {
#pragma unroll
            for (int kk = 0; kk < 4; kk++) {
                const uint32_t rb = (kg * 16 + bRowK) * PITCHB + kk * 32 + bColK;
                uint32_t th[4], tl[4];
                ldsm_x4(th, stg + rb);
                ldsm_x4(tl, stg + 9216 + rb);
                uint32_t b0h[2] = {th[0], th[1]}, b1h[2] = {th[2], th[3]};
                uint32_t b0l[2] = {tl[0], tl[1]}, b1l[2] = {tl[2], tl[3]};
                mma_bf16(sacc[2 * kg],     ah[kk], b0h);
                mma_bf16(sacc[2 * kg],     al[kk], b0h);
                mma_bf16(sacc[2 * kg],     ah[kk], b0l);
                mma_bf16(sacc[2 * kg + 1], ah[kk], b1h);
                mma_bf16(sacc[2 * kg + 1], al[kk], b1h);
                mma_bf16(sacc[2 * kg + 1], ah[kk], b1l);
            }
        }

        // ---- online softmax ----
        float cm0 = sacc[0][0], cm1 = sacc[0][2];
#pragma unroll
        for (int j = 0; j < 8; j++) {
            cm0 = fmaxf(cm0, fmaxf(sacc[j][0], sacc[j][1]));
            cm1 = fmaxf(cm1, fmaxf(sacc[j][2], sacc[j][3]));
        }
        cm0 = fmaxf(cm0, __shfl_xor_sync(0xffffffffu, cm0, 1));
        cm0 = fmaxf(cm0, __shfl_xor_sync(0xffffffffu, cm0, 2));
        cm1 = fmaxf(cm1, __shfl_xor_sync(0xffffffffu, cm1, 1));
        cm1 = fmaxf(cm1, __shfl_xor_sync(0xffffffffu, cm1, 2));
        const float mn0 = fmaxf(mr0, cm0);
        const float mn1 = fmaxf(mr1, cm1);
        const float cr0 = __expf(mr0 - mn0);
        const float cr1 = __expf(mr1 - mn1);
        mr0 = mn0; mr1 = mn1;
#pragma unroll
        for (int j = 0; j < 8; j++) {
            Oc[j][0] *= cr0; Oc[j][1] *= cr0;
            Oc[j][2] *= cr1; Oc[j][3] *= cr1;
        }
        float sum0 = 0.f, sum1 = 0.f;
#pragma unroll
        for (int j = 0; j < 8; j++) {
            sacc[j][0] = __expf(sacc[j][0] - mn0);
            sacc[j][1] = __expf(sacc[j][1] - mn0);
            sacc[j][2] = __expf(sacc[j][2] - mn1);
            sacc[j][3] = __expf(sacc[j][3] - mn1);
            sum0 += sacc[j][0] + sacc[j][1];
            sum1 += sacc[j][2] + sacc[j][3];
        }
        sum0 += __shfl_xor_sync(0xffffffffu, sum0, 1);
        sum0 += __shfl_xor_sync(0xffffffffu, sum0, 2);
        sum1 += __shfl_xor_sync(0xffffffffu, sum1, 1);
        sum1 += __shfl_xor_sync(0xffffffffu, sum1, 2);
        lr0 = lr0 * cr0 + sum0;
        lr1 = lr1 * cr1 + sum1;

        // ---- O += P V ----
#pragma unroll
        for (int kk2 = 0; kk2 < 4; kk2++) {
            // build P A-fragments (hi/lo split) from sacc.
            // A-frag order (validated by R4 GEMM): {(r,k0-7),(r+8,k0-7),(r,k8-15),(r+8,k8-15)}
            // = {L.c01, L.c23, R.c01, R.c23} for left/right 8-key C tiles. No swap.
            uint32_t aph[4], apl[4];
#pragma unroll
            for (int f = 0; f < 2; f++) {
                const float* p = sacc[2 * kk2 + f];
                __nv_bfloat16 h0 = __float2bfloat16(p[0]);
                __nv_bfloat16 h1 = __float2bfloat16(p[1]);
                __nv_bfloat16 h2 = __float2bfloat16(p[2]);
                __nv_bfloat16 h3 = __float2bfloat16(p[3]);
                aph[2 * f]     = pack2bf(__bfloat162float(h0), __bfloat162float(h1));
                aph[2 * f + 1] = pack2bf(__bfloat162float(h2), __bfloat162float(h3));
                apl[2 * f]     = pack2bf(p[0] - __bfloat162float(h0),
                                         p[1] - __bfloat162float(h1));
                apl[2 * f + 1] = pack2bf(p[2] - __bfloat162float(h2),
                                         p[3] - __bfloat162float(h3));
            }
#pragma unroll
            for (int ng2 = 0; ng2 < 4; ng2++) {
                const uint32_t rv = (kk2 * 16 + vRow) * PITCHB + ng2 * 32 + vColB;
                uint32_t th[4], tl[4];
                ldsm_x4t(th, stg + 18432 + rv);
                ldsm_x4t(tl, stg + 27648 + rv);
                uint32_t b0h[2] = {th[0], th[1]}, b1h[2] = {th[2], th[3]};
                uint32_t b0l[2] = {tl[0], tl[1]}, b1l[2] = {tl[2], tl[3]};
                mma_bf16(Oc[2 * ng2],     aph, b0h);
                mma_bf16(Oc[2 * ng2],     apl, b0h);
                mma_bf16(Oc[2 * ng2],     aph, b0l);
                mma_bf16(Oc[2 * ng2 + 1], aph, b1h);
                mma_bf16(Oc[2 * ng2 + 1], apl, b1h);
                mma_bf16(Oc[2 * ng2 + 1], aph, b1l);
            }
        }
        __syncthreads();   // protect stage buffer before next prefetch
    }

    // ---- epilogue: normalize, split, store ctx ----
    const float inv0 = 1.f / lr0;
    const float inv1 = 1.f / lr1;
    const int r0 = m0 + wid * 16 + (lane >> 2);
#pragma unroll
    for (int j = 0; j < 8; j++) {
        const int col = dcol + j * 8 + ((lane & 3) << 1);
        split_store(g_ch, g_cl, (size_t)r0 * DM + col,
                    Oc[j][0] * inv0, Oc[j][1] * inv0);
        split_store(g_ch, g_cl, (size_t)(r0 + 8) * DM + col,
                    Oc[j][2] * inv1, Oc[j][3] * inv1);
    }
}

// ---------------------------------------------------------------------------
extern "C" void kernel_launch(void* const* d_in, const int* in_sizes, int n_in,
                              void* d_out, int out_size)
{
    const float* x    = (const float*)d_in[0];
    const int*   gate = (const int*)  d_in[1];
    const float* Wq   = (const float*)d_in[2];
    const float* bq   = (const float*)d_in[3];
    const float* Wk   = (const float*)d_in[4];
    const float* bk   = (const float*)d_in[5];
    const float* Wv   = (const float*)d_in[6];
    const float* bv   = (const float*)d_in[7];
    const float* Wo   = (const float*)d_in[8];
    const float* bo   = (const float*)d_in[9];
    float* out = (float*)d_out;

    cudaFuncSetAttribute(gemm_mma<0>, cudaFuncAttributeMaxDynamicSharedMemorySize, GSMEM_TOT);
    cudaFuncSetAttribute(gemm_mma<3>, cudaFuncAttributeMaxDynamicSharedMemorySize, GSMEM_TOT);
    cudaFuncSetAttribute(attn_mma, cudaFuncAttributeMaxDynamicSharedMemorySize, AT_SMEM);

    conv_split<<<MTOT * DM / 1024, 256>>>(x);
    conv_w<<<dim3(32, 32), dim3(32, 8)>>>(Wq, 0);
    conv_w<<<dim3(32, 32), dim3(32, 8)>>>(Wk, 1);
    conv_w<<<dim3(32, 32), dim3(32, 8)>>>(Wv, 2);
    conv_w<<<dim3(32, 32), dim3(32, 8)>>>(Wo, 3);

    gemm_mma<0><<<dim3(DM / 128, MTOT / 128, 3), 256, GSMEM_TOT>>>(
        bq, bk, bv, gate, x, nullptr);

    attn_mma<<<dim3(S_ / 128, HEADS, B_), 256, AT_SMEM>>>();

    gemm_mma<3><<<dim3(DM / 128, MTOT / 128), 256, GSMEM_TOT>>>(
        bo, nullptr, nullptr, gate, x, out);
}

// round 7
// speedup vs baseline: 8.5342x; 1.3569x over previous
#include <cuda_runtime.h>
#include <cuda_bf16.h>
#include <cstdint>
#include <cstddef>

#define DM 1024
#define HEADS 16
#define HD 64
#define B_ 2
#define S_ 2048
#define MTOT 4096   // B*S

// ---------------------------------------------------------------------------
// Scratch (__device__ globals; allocation-free rule). All split-bf16.
// ---------------------------------------------------------------------------
__device__ __nv_bfloat16 g_xh[MTOT * DM];
__device__ __nv_bfloat16 g_xl[MTOT * DM];
__device__ __nv_bfloat16 g_qh[MTOT * DM];   // pre-scaled by 1/8
__device__ __nv_bfloat16 g_ql[MTOT * DM];
__device__ __nv_bfloat16 g_kh[MTOT * DM];
__device__ __nv_bfloat16 g_kl[MTOT * DM];
__device__ __nv_bfloat16 g_vh[MTOT * DM];
__device__ __nv_bfloat16 g_vl[MTOT * DM];
__device__ __nv_bfloat16 g_ch[MTOT * DM];   // attention context (COMPACTED rows)
__device__ __nv_bfloat16 g_cl[MTOT * DM];
__device__ __nv_bfloat16 g_wh[4][DM * DM];  // W^T hi, [n][k]
__device__ __nv_bfloat16 g_wl[4][DM * DM];  // W^T lo, [n][k]
__device__ int g_nact[B_];                  // active tokens per batch
__device__ int g_idx[B_ * S_];              // compacted active token positions

// ---------------------------------------------------------------------------
// sm_100-safe PTX helpers
// ---------------------------------------------------------------------------
__device__ __forceinline__ uint32_t smem_u32(const void* p) {
    uint32_t a;
    asm("{ .reg .u64 t; cvta.to.shared.u64 t, %1; cvt.u32.u64 %0, t; }"
        : "=r"(a) : "l"(p));
    return a;
}
__device__ __forceinline__ void ldsm_x4(uint32_t* r, uint32_t addr) {
    asm volatile("ldmatrix.sync.aligned.m8n8.x4.shared.b16 {%0,%1,%2,%3}, [%4];"
                 : "=r"(r[0]), "=r"(r[1]), "=r"(r[2]), "=r"(r[3]) : "r"(addr));
}
__device__ __forceinline__ void ldsm_x4t(uint32_t* r, uint32_t addr) {
    asm volatile("ldmatrix.sync.aligned.m8n8.x4.trans.shared.b16 {%0,%1,%2,%3}, [%4];"
                 : "=r"(r[0]), "=r"(r[1]), "=r"(r[2]), "=r"(r[3]) : "r"(addr));
}
__device__ __forceinline__ void mma_bf16(float* d, const uint32_t* a, const uint32_t* b) {
    asm volatile(
        "mma.sync.aligned.m16n8k16.row.col.f32.bf16.bf16.f32 "
        "{%0,%1,%2,%3},{%4,%5,%6,%7},{%8,%9},{%0,%1,%2,%3};"
        : "+f"(d[0]), "+f"(d[1]), "+f"(d[2]), "+f"(d[3])
        : "r"(a[0]), "r"(a[1]), "r"(a[2]), "r"(a[3]), "r"(b[0]), "r"(b[1]));
}
__device__ __forceinline__ void cp16(uint32_t s, const void* g) {
    asm volatile("cp.async.cg.shared.global [%0], [%1], 16;" :: "r"(s), "l"(g));
}
#define CP_COMMIT() asm volatile("cp.async.commit_group;" ::: "memory")
#define CP_WAIT0()  asm volatile("cp.async.wait_group 0;" ::: "memory")
#define CP_WAIT1()  asm volatile("cp.async.wait_group 1;" ::: "memory")

__device__ __forceinline__ uint32_t pack2bf(float lo, float hi) {
    uint32_t r;
    asm("cvt.rn.bf16x2.f32 %0, %1, %2;" : "=r"(r) : "f"(hi), "f"(lo));
    return r;
}
__device__ __forceinline__ void split_store(__nv_bfloat16* ph, __nv_bfloat16* pl,
                                            size_t off, float v0, float v1) {
    __nv_bfloat16 h0 = __float2bfloat16(v0);
    __nv_bfloat16 h1 = __float2bfloat16(v1);
    __nv_bfloat16 l0 = __float2bfloat16(v0 - __bfloat162float(h0));
    __nv_bfloat16 l1 = __float2bfloat16(v1 - __bfloat162float(h1));
    *(__nv_bfloat162*)(ph + off) = __nv_bfloat162(h0, h1);
    *(__nv_bfloat162*)(pl + off) = __nv_bfloat162(l0, l1);
}

// ---------------------------------------------------------------------------
// Gate compaction: per batch, list of active token positions + count.
// ---------------------------------------------------------------------------
__global__ void build_idx(const int* __restrict__ gate)
{
    const int b = blockIdx.x;
    const int tid = threadIdx.x;        // 256 threads, 8 tokens each
    __shared__ int cnt[256];
    const int base = b * S_ + tid * 8;
    int gv[8];
    int c = 0;
#pragma unroll
    for (int i = 0; i < 8; i++) { gv[i] = gate[base + i]; c += gv[i]; }
    cnt[tid] = c;
    __syncthreads();
    for (int off = 1; off < 256; off <<= 1) {
        int t = (tid >= off) ? cnt[tid - off] : 0;
        __syncthreads();
        cnt[tid] += t;
        __syncthreads();
    }
    int o = cnt[tid] - c;               // exclusive prefix
    if (tid == 255) g_nact[b] = cnt[255];
#pragma unroll
    for (int i = 0; i < 8; i++)
        if (gv[i]) g_idx[b * S_ + (o++)] = tid * 8 + i;
}

// out = x (covers inactive rows; active rows overwritten by O-proj)
__global__ void copy_x(const float* __restrict__ x, float* __restrict__ out)
{
    const int i = (blockIdx.x * blockDim.x + threadIdx.x) * 4;
    *(float4*)(out + i) = *(const float4*)(x + i);
}

// ---------------------------------------------------------------------------
// fp32 x -> bf16 hi/lo split
// ---------------------------------------------------------------------------
__global__ void conv_split(const float* __restrict__ src)
{
    const int i = (blockIdx.x * blockDim.x + threadIdx.x) * 4;
    float4 v = *(const float4*)(src + i);
    split_store(g_xh, g_xl, i, v.x, v.y);
    split_store(g_xh, g_xl, i + 2, v.z, v.w);
}

// ---------------------------------------------------------------------------
// W [K][N] fp32 -> transposed bf16 hi/lo splits g_wh/g_wl[widx] as [n][k]
// ---------------------------------------------------------------------------
__global__ void conv_w(const float* __restrict__ W, int widx)
{
    __shared__ float t[32][33];
    const int k0 = blockIdx.y * 32, n0 = blockIdx.x * 32;
    const int tx = threadIdx.x, ty = threadIdx.y;
#pragma unroll
    for (int i = 0; i < 4; i++)
        t[ty + i * 8][tx] = W[(size_t)(k0 + ty + i * 8) * DM + n0 + tx];
    __syncthreads();
    __nv_bfloat16* ph = g_wh[widx];
    __nv_bfloat16* pl = g_wl[widx];
#pragma unroll
    for (int i = 0; i < 4; i++) {
        float v = t[tx][ty + i * 8];
        __nv_bfloat16 hh = __float2bfloat16(v);
        __nv_bfloat16 ll = __float2bfloat16(v - __bfloat162float(hh));
        ph[(size_t)(n0 + ty + i * 8) * DM + k0 + tx] = hh;
        pl[(size_t)(n0 + ty + i * 8) * DM + k0 + tx] = ll;
    }
}

// ---------------------------------------------------------------------------
// Split-bf16 HMMA GEMM.
// MODE 0: fused QKV, dense (blockIdx.z = 0/1/2 -> q/k/v, gated, Q/8)
// MODE 3: O proj on COMPACTED ctx rows; scatters out[tok] = ctx@Wo + bo
//         (g=1 for all active rows; inactive rows already hold x).
// ---------------------------------------------------------------------------
#define TILE_B 10240                      // 128*40*2 bytes
#define STAGE_B (4 * TILE_B)              // 40960
#define GSMEM_TOT (2 * STAGE_B)           // 81920

template <int MODE>
__global__ __launch_bounds__(256, 1) void gemm_mma(
    const float* __restrict__ bias0, const float* __restrict__ bias1,
    const float* __restrict__ bias2, const int* __restrict__ gate,
    float* __restrict__ Cout)
{
    extern __shared__ char smem[];
    const uint32_t sb = smem_u32(smem);
    const int tid = threadIdx.x;
    const int wid = tid >> 5;
    const int lane = tid & 31;
    const int wm = wid >> 2;
    const int wn = wid & 3;
    const int n0 = blockIdx.x * 128;

    int m0, bb = 0, nact = 0, jbase = 0;
    if (MODE == 3) {
        bb = blockIdx.z;
        nact = g_nact[bb];
        jbase = blockIdx.y * 128;
        if (jbase >= nact) return;
        m0 = bb * S_ + jbase;            // compacted row base
    } else {
        m0 = blockIdx.y * 128;           // dense row base
    }
    const int z = (MODE == 0) ? blockIdx.z : 3;

    const __nv_bfloat16* Ah = (MODE == 3) ? g_ch : g_xh;
    const __nv_bfloat16* Al = (MODE == 3) ? g_cl : g_xl;
    const __nv_bfloat16* Bh = g_wh[z];
    const __nv_bfloat16* Bl = g_wl[z];
    const float* bias = (MODE == 3) ? bias0 : (z == 0 ? bias0 : (z == 1 ? bias1 : bias2));
    __nv_bfloat16* Oh = nullptr;
    __nv_bfloat16* Ol = nullptr;
    if (MODE == 0) {
        Oh = (z == 0) ? g_qh : (z == 1) ? g_kh : g_vh;
        Ol = (z == 0) ? g_ql : (z == 1) ? g_kl : g_vl;
    }

    float acc[4][4][4];
#pragma unroll
    for (int i = 0; i < 4; i++)
#pragma unroll
        for (int j = 0; j < 4; j++)
#pragma unroll
            for (int e = 0; e < 4; e++) acc[i][j][e] = 0.f;

    const int lrow = tid >> 1;
    const int lc0 = (tid & 1) * 2;

    auto load_stage = [&](int st, int kc) {
        const int k0 = kc * 32;
        const uint32_t sbase = sb + st * STAGE_B;
        const size_t goA = (size_t)(m0 + lrow) * DM + k0;
        const size_t goB = (size_t)(n0 + lrow) * DM + k0;
#pragma unroll
        for (int c = 0; c < 2; c++) {
            const int ch = lc0 + c;
            const uint32_t so = lrow * 80 + ch * 16;
            cp16(sbase + so,              Ah + goA + ch * 8);
            cp16(sbase + TILE_B + so,     Al + goA + ch * 8);
            cp16(sbase + 2 * TILE_B + so, Bh + goB + ch * 8);
            cp16(sbase + 3 * TILE_B + so, Bl + goB + ch * 8);
        }
    };

    const int aRowOff = lane & 15;
    const int aColB0 = ((lane >> 4) << 3) * 2;
    const int bRowOff = (lane & 7) + ((lane >> 4) << 3);
    const int bColB0 = (((lane >> 3) & 1) << 3) * 2;

    load_stage(0, 0);
    CP_COMMIT();
    CP_WAIT0();
    __syncthreads();

    const int NCH = DM / 32;
    for (int kc = 0; kc < NCH; kc++) {
        const int cur = kc & 1;
        if (kc + 1 < NCH) { load_stage(1 - cur, kc + 1); CP_COMMIT(); }

        const uint32_t stb = sb + cur * STAGE_B;
#pragma unroll
        for (int ks = 0; ks < 2; ks++) {
            uint32_t ah[4][4], al[4][4], bh[4][2], bl[4][2];
            const int kB = ks * 32;
#pragma unroll
            for (int mf = 0; mf < 4; mf++) {
                const uint32_t ra = (wm * 64 + mf * 16 + aRowOff) * 80 + kB + aColB0;
                ldsm_x4(ah[mf], stb + ra);
                ldsm_x4(al[mf], stb + TILE_B + ra);
            }
#pragma unroll
            for (int np = 0; np < 2; np++) {
                const uint32_t rb = (wn * 32 + np * 16 + bRowOff) * 80 + kB + bColB0;
                uint32_t t[4];
                ldsm_x4(t, stb + 2 * TILE_B + rb);
                bh[np * 2][0] = t[0]; bh[np * 2][1] = t[1];
                bh[np * 2 + 1][0] = t[2]; bh[np * 2 + 1][1] = t[3];
                ldsm_x4(t, stb + 3 * TILE_B + rb);
                bl[np * 2][0] = t[0]; bl[np * 2][1] = t[1];
                bl[np * 2 + 1][0] = t[2]; bl[np * 2 + 1][1] = t[3];
            }
#pragma unroll
            for (int mf = 0; mf < 4; mf++)
#pragma unroll
                for (int nf = 0; nf < 4; nf++) {
                    mma_bf16(acc[mf][nf], ah[mf], bh[nf]);
                    mma_bf16(acc[mf][nf], ah[mf], bl[nf]);
                    mma_bf16(acc[mf][nf], al[mf], bh[nf]);
                }
        }
        if (kc + 1 < NCH) { CP_WAIT0(); __syncthreads(); }
    }

    const float qs = (MODE == 0 && z == 0) ? 0.125f : 1.0f;
#pragma unroll
    for (int mf = 0; mf < 4; mf++) {
#pragma unroll
        for (int half = 0; half < 2; half++) {
            const int rl = wm * 64 + mf * 16 + (lane >> 2) + half * 8;  // 0..127
#pragma unroll
            for (int nf = 0; nf < 4; nf++) {
                const int col = n0 + wn * 32 + nf * 8 + ((lane & 3) << 1);
                float v0 = acc[mf][nf][half * 2 + 0] + bias[col];
                float v1 = acc[mf][nf][half * 2 + 1] + bias[col + 1];
                if (MODE == 0) {
                    const int r = m0 + rl;
                    const float gm = (float)gate[r] * qs;
                    split_store(Oh, Ol, (size_t)r * DM + col, v0 * gm, v1 * gm);
                } else {
                    const int j = jbase + rl;
                    if (j < nact) {
                        const int tok = g_idx[bb * S_ + j];
                        float2 o; o.x = v0; o.y = v1;
                        *(float2*)(Cout + (size_t)(bb * S_ + tok) * DM + col) = o;
                    }
                }
            }
        }
    }
}

// ---------------------------------------------------------------------------
// mma.sync flash attention, split-bf16 3-pass, gate-compacted query rows.
// CTA: 128 compacted query rows of one (b,h). Keys/values stay dense.
// ---------------------------------------------------------------------------
#define AT_STG0  36864
#define AT_STGSZ 36864
#define AT_SMEM  (AT_STG0 + 2 * AT_STGSZ)   // 110592
#define PITCHB   144

__device__ __forceinline__ void prefetch_kv(uint32_t sb, int b, int kt, int st,
                                            int dcol, int tid)
{
    const uint32_t stg = sb + AT_STG0 + st * AT_STGSZ;
    const int gb = b * S_ + kt * 64;
#pragma unroll
    for (int t = 0; t < 8; t++) {
        const __nv_bfloat16* src =
            (t < 2) ? g_kh : (t < 4) ? g_kl : (t < 6) ? g_vh : g_vl;
        const int arr = t >> 1;
        const int rem = (tid + t * 256) - arr * 512;   // 0..511
        const int row = rem >> 3, ch = rem & 7;
        cp16(stg + arr * 9216 + row * PITCHB + ch * 16,
             src + (size_t)(gb + row) * DM + dcol + ch * 8);
    }
}

__global__ __launch_bounds__(256, 1) void attn_mma()
{
    extern __shared__ char smem[];
    const uint32_t sb = smem_u32(smem);
    const int tid = threadIdx.x, wid = tid >> 5, lane = tid & 31;
    const int qt = blockIdx.x, h = blockIdx.y, b = blockIdx.z;
    const int nact = g_nact[b];
    if (qt * 128 >= nact) return;
    const int dcol = h * HD;

    // issue Q tile (gathered via g_idx) + stage 0 K/V
#pragma unroll
    for (int t = 0; t < 8; t++) {
        const __nv_bfloat16* src = (t < 4) ? g_qh : g_ql;
        const int arr = t >> 2;
        const int rem = (tid + t * 256) - arr * 1024;  // 0..1023
        const int row = rem >> 3, ch = rem & 7;
        int j = qt * 128 + row;
        if (j >= nact) j = nact - 1;
        const int tok = g_idx[b * S_ + j];
        cp16(sb + arr * 18432 + row * PITCHB + ch * 16,
             src + (size_t)(b * S_ + tok) * DM + dcol + ch * 8);
    }
    prefetch_kv(sb, b, 0, 0, dcol, tid);
    CP_COMMIT();
    CP_WAIT0();
    __syncthreads();

    // Q A-fragments (held in regs for the whole loop)
    uint32_t ah[4][4], al[4][4];
    {
        const int aRow = lane & 15;
        const int aCol = (lane >> 4) * 16;
#pragma unroll
        for (int kk = 0; kk < 4; kk++) {
            const uint32_t ra = (wid * 16 + aRow) * PITCHB + kk * 32 + aCol;
            ldsm_x4(ah[kk], sb + ra);
            ldsm_x4(al[kk], sb + 18432 + ra);
        }
    }

    float Oc[8][4];
#pragma unroll
    for (int j = 0; j < 8; j++)
#pragma unroll
        for (int e = 0; e < 4; e++) Oc[j][e] = 0.f;
    float mr0 = -1e30f, mr1 = -1e30f, lr0 = 0.f, lr1 = 0.f;

    const int bRowK = (lane & 7) + ((lane >> 4) << 3);
    const int bColK = ((lane >> 3) & 1) * 16;
    const int vRow = (lane & 7) + (((lane >> 3) & 1) << 3);
    const int vColB = ((lane >> 4) << 3) * 2;

    for (int kt = 0; kt < 32; kt++) {
        if (kt + 1 < 32) {
            prefetch_kv(sb, b, kt + 1, (kt + 1) & 1, dcol, tid);
            CP_COMMIT();
            CP_WAIT1();
        } else {
            CP_WAIT0();
        }
        __syncthreads();
        const uint32_t stg = sb + AT_STG0 + (kt & 1) * AT_STGSZ;

        // ---- S = Q K^T ----
        float sacc[8][4];
#pragma unroll
        for (int j = 0; j < 8; j++)
#pragma unroll
            for (int e = 0; e < 4; e++) sacc[j][e] = 0.f;

#pragma unroll
        for (int kg = 0; kg < 4; kg++) {
#pragma unroll
            for (int kk = 0; kk < 4; kk++) {
                const uint32_t rb = (kg * 16 + bRowK) * PITCHB + kk * 32 + bColK;
                uint32_t th[4], tl[4];
                ldsm_x4(th, stg + rb);
                ldsm_x4(tl, stg + 9216 + rb);
                uint32_t b0h[2] = {th[0], th[1]}, b1h[2] = {th[2], th[3]};
                uint32_t b0l[2] = {tl[0], tl[1]}, b1l[2] = {tl[2], tl[3]};
                mma_bf16(sacc[2 * kg],     ah[kk], b0h);
                mma_bf16(sacc[2 * kg],     al[kk], b0h);
                mma_bf16(sacc[2 * kg],     ah[kk], b0l);
                mma_bf16(sacc[2 * kg + 1], ah[kk], b1h);
                mma_bf16(sacc[2 * kg + 1], al[kk], b1h);
                mma_bf16(sacc[2 * kg + 1], ah[kk], b1l);
            }
        }

        // ---- online softmax ----
        float cm0 = sacc[0][0], cm1 = sacc[0][2];
#pragma unroll
        for (int j = 0; j < 8; j++) {
            cm0 = fmaxf(cm0, fmaxf(sacc[j][0], sacc[j][1]));
            cm1 = fmaxf(cm1, fmaxf(sacc[j][2], sacc[j][3]));
        }
        cm0 = fmaxf(cm0, __shfl_xor_sync(0xffffffffu, cm0, 1));
        cm0 = fmaxf(cm0, __shfl_xor_sync(0xffffffffu, cm0, 2));
        cm1 = fmaxf(cm1, __shfl_xor_sync(0xffffffffu, cm1, 1));
        cm1 = fmaxf(cm1, __shfl_xor_sync(0xffffffffu, cm1, 2));
        const float mn0 = fmaxf(mr0, cm0);
        const float mn1 = fmaxf(mr1, cm1);
        const float cr0 = __expf(mr0 - mn0);
        const float cr1 = __expf(mr1 - mn1);
        mr0 = mn0; mr1 = mn1;
#pragma unroll
        for (int j = 0; j < 8; j++) {
            Oc[j][0] *= cr0; Oc[j][1] *= cr0;
            Oc[j][2] *= cr1; Oc[j][3] *= cr1;
        }
        float sum0 = 0.f, sum1 = 0.f;
#pragma unroll
        for (int j = 0; j < 8; j++) {
            sacc[j][0] = __expf(sacc[j][0] - mn0);
            sacc[j][1] = __expf(sacc[j][1] - mn0);
            sacc[j][2] = __expf(sacc[j][2] - mn1);
            sacc[j][3] = __expf(sacc[j][3] - mn1);
            sum0 += sacc[j][0] + sacc[j][1];
            sum1 += sacc[j][2] + sacc[j][3];
        }
        sum0 += __shfl_xor_sync(0xffffffffu, sum0, 1);
        sum0 += __shfl_xor_sync(0xffffffffu, sum0, 2);
        sum1 += __shfl_xor_sync(0xffffffffu, sum1, 1);
        sum1 += __shfl_xor_sync(0xffffffffu, sum1, 2);
        lr0 = lr0 * cr0 + sum0;
        lr1 = lr1 * cr1 + sum1;

        // ---- O += P V ----
#pragma unroll
        for (int kk2 = 0; kk2 < 4; kk2++) {
            uint32_t aph[4], apl[4];
#pragma unroll
            for (int f = 0; f < 2; f++) {
                const float* p = sacc[2 * kk2 + f];
                __nv_bfloat16 h0 = __float2bfloat16(p[0]);
                __nv_bfloat16 h1 = __float2bfloat16(p[1]);
                __nv_bfloat16 h2 = __float2bfloat16(p[2]);
                __nv_bfloat16 h3 = __float2bfloat16(p[3]);
                aph[2 * f]     = pack2bf(__bfloat162float(h0), __bfloat162float(h1));
                aph[2 * f + 1] = pack2bf(__bfloat162float(h2), __bfloat162float(h3));
                apl[2 * f]     = pack2bf(p[0] - __bfloat162float(h0),
                                         p[1] - __bfloat162float(h1));
                apl[2 * f + 1] = pack2bf(p[2] - __bfloat162float(h2),
                                         p[3] - __bfloat162float(h3));
            }
#pragma unroll
            for (int ng2 = 0; ng2 < 4; ng2++) {
                const uint32_t rv = (kk2 * 16 + vRow) * PITCHB + ng2 * 32 + vColB;
                uint32_t th[4], tl[4];
                ldsm_x4t(th, stg + 18432 + rv);
                ldsm_x4t(tl, stg + 27648 + rv);
                uint32_t b0h[2] = {th[0], th[1]}, b1h[2] = {th[2], th[3]};
                uint32_t b0l[2] = {tl[0], tl[1]}, b1l[2] = {tl[2], tl[3]};
                mma_bf16(Oc[2 * ng2],     aph, b0h);
                mma_bf16(Oc[2 * ng2],     apl, b0h);
                mma_bf16(Oc[2 * ng2],     aph, b0l);
                mma_bf16(Oc[2 * ng2 + 1], aph, b1h);
                mma_bf16(Oc[2 * ng2 + 1], apl, b1h);
                mma_bf16(Oc[2 * ng2 + 1], aph, b1l);
            }
        }
        __syncthreads();
    }

    // ---- epilogue: normalize, split, store ctx at COMPACTED rows ----
    const float inv0 = 1.f / lr0;
    const float inv1 = 1.f / lr1;
    const int jl = wid * 16 + (lane >> 2);
    const int j0 = qt * 128 + jl;
    const int j1 = j0 + 8;
#pragma unroll
    for (int j = 0; j < 8; j++) {
        const int col = dcol + j * 8 + ((lane & 3) << 1);
        if (j0 < nact)
            split_store(g_ch, g_cl, (size_t)(b * S_ + j0) * DM + col,
                        Oc[j][0] * inv0, Oc[j][1] * inv0);
        if (j1 < nact)
            split_store(g_ch, g_cl, (size_t)(b * S_ + j1) * DM + col,
                        Oc[j][2] * inv1, Oc[j][3] * inv1);
    }
}

// ---------------------------------------------------------------------------
extern "C" void kernel_launch(void* const* d_in, const int* in_sizes, int n_in,
                              void* d_out, int out_size)
{
    const float* x    = (const float*)d_in[0];
    const int*   gate = (const int*)  d_in[1];
    const float* Wq   = (const float*)d_in[2];
    const float* bq   = (const float*)d_in[3];
    const float* Wk   = (const float*)d_in[4];
    const float* bk   = (const float*)d_in[5];
    const float* Wv   = (const float*)d_in[6];
    const float* bv   = (const float*)d_in[7];
    const float* Wo   = (const float*)d_in[8];
    const float* bo   = (const float*)d_in[9];
    float* out = (float*)d_out;

    cudaFuncSetAttribute(gemm_mma<0>, cudaFuncAttributeMaxDynamicSharedMemorySize, GSMEM_TOT);
    cudaFuncSetAttribute(gemm_mma<3>, cudaFuncAttributeMaxDynamicSharedMemorySize, GSMEM_TOT);
    cudaFuncSetAttribute(attn_mma, cudaFuncAttributeMaxDynamicSharedMemorySize, AT_SMEM);

    build_idx<<<B_, 256>>>(gate);
    copy_x<<<MTOT * DM / 1024, 256>>>(x, out);
    conv_split<<<MTOT * DM / 1024, 256>>>(x);
    conv_w<<<dim3(32, 32), dim3(32, 8)>>>(Wq, 0);
    conv_w<<<dim3(32, 32), dim3(32, 8)>>>(Wk, 1);
    conv_w<<<dim3(32, 32), dim3(32, 8)>>>(Wv, 2);
    conv_w<<<dim3(32, 32), dim3(32, 8)>>>(Wo, 3);

    gemm_mma<0><<<dim3(DM / 128, MTOT / 128, 3), 256, GSMEM_TOT>>>(
        bq, bk, bv, gate, nullptr);

    attn_mma<<<dim3(S_ / 128, HEADS, B_), 256, AT_SMEM>>>();

    gemm_mma<3><<<dim3(DM / 128, S_ / 128, B_), 256, GSMEM_TOT>>>(
        bo, nullptr, nullptr, gate, out);
}

// round 8
// speedup vs baseline: 19.3389x; 2.2660x over previous
#include <cuda_runtime.h>
#include <cuda_fp16.h>
#include <cstdint>
#include <cstddef>

#define DM 1024
#define HEADS 16
#define HD 64
#define B_ 2
#define S_ 2048
#define MTOT 4096   // B*S

// ---------------------------------------------------------------------------
// Scratch (__device__ globals; allocation-free rule). Single fp16.
// ---------------------------------------------------------------------------
__device__ __half g_x[MTOT * DM];
__device__ __half g_q[MTOT * DM];   // pre-scaled by 1/8, gated
__device__ __half g_k[MTOT * DM];
__device__ __half g_v[MTOT * DM];
__device__ __half g_c[MTOT * DM];   // attention context (COMPACTED rows)
__device__ __half g_w[4][DM * DM];  // W^T, [n][k]
__device__ int g_nact[B_];
__device__ int g_idx[B_ * S_];

// ---------------------------------------------------------------------------
// sm_100-safe PTX helpers
// ---------------------------------------------------------------------------
__device__ __forceinline__ uint32_t smem_u32(const void* p) {
    uint32_t a;
    asm("{ .reg .u64 t; cvta.to.shared.u64 t, %1; cvt.u32.u64 %0, t; }"
        : "=r"(a) : "l"(p));
    return a;
}
__device__ __forceinline__ void ldsm_x4(uint32_t* r, uint32_t addr) {
    asm volatile("ldmatrix.sync.aligned.m8n8.x4.shared.b16 {%0,%1,%2,%3}, [%4];"
                 : "=r"(r[0]), "=r"(r[1]), "=r"(r[2]), "=r"(r[3]) : "r"(addr));
}
__device__ __forceinline__ void ldsm_x4t(uint32_t* r, uint32_t addr) {
    asm volatile("ldmatrix.sync.aligned.m8n8.x4.trans.shared.b16 {%0,%1,%2,%3}, [%4];"
                 : "=r"(r[0]), "=r"(r[1]), "=r"(r[2]), "=r"(r[3]) : "r"(addr));
}
__device__ __forceinline__ void mma_f16(float* d, const uint32_t* a, const uint32_t* b) {
    asm volatile(
        "mma.sync.aligned.m16n8k16.row.col.f32.f16.f16.f32 "
        "{%0,%1,%2,%3},{%4,%5,%6,%7},{%8,%9},{%0,%1,%2,%3};"
        : "+f"(d[0]), "+f"(d[1]), "+f"(d[2]), "+f"(d[3])
        : "r"(a[0]), "r"(a[1]), "r"(a[2]), "r"(a[3]), "r"(b[0]), "r"(b[1]));
}
__device__ __forceinline__ void cp16(uint32_t s, const void* g) {
    asm volatile("cp.async.cg.shared.global [%0], [%1], 16;" :: "r"(s), "l"(g));
}
#define CP_COMMIT() asm volatile("cp.async.commit_group;" ::: "memory")
#define CP_WAIT0()  asm volatile("cp.async.wait_group 0;" ::: "memory")
#define CP_WAIT1()  asm volatile("cp.async.wait_group 1;" ::: "memory")

__device__ __forceinline__ uint32_t pack2h(float lo, float hi) {
    uint32_t r;
    asm("cvt.rn.f16x2.f32 %0, %1, %2;" : "=r"(r) : "f"(hi), "f"(lo));
    return r;
}

// ---------------------------------------------------------------------------
// Gate compaction
// ---------------------------------------------------------------------------
__global__ void build_idx(const int* __restrict__ gate)
{
    const int b = blockIdx.x;
    const int tid = threadIdx.x;
    __shared__ int cnt[256];
    const int base = b * S_ + tid * 8;
    int gv[8];
    int c = 0;
#pragma unroll
    for (int i = 0; i < 8; i++) { gv[i] = gate[base + i]; c += gv[i]; }
    cnt[tid] = c;
    __syncthreads();
    for (int off = 1; off < 256; off <<= 1) {
        int t = (tid >= off) ? cnt[tid - off] : 0;
        __syncthreads();
        cnt[tid] += t;
        __syncthreads();
    }
    int o = cnt[tid] - c;
    if (tid == 255) g_nact[b] = cnt[255];
#pragma unroll
    for (int i = 0; i < 8; i++)
        if (gv[i]) g_idx[b * S_ + (o++)] = tid * 8 + i;
}

// ---------------------------------------------------------------------------
// x -> fp16 scratch, and out = x (inactive rows keep x; active overwritten)
// ---------------------------------------------------------------------------
__global__ void conv_x(const float* __restrict__ x, float* __restrict__ out)
{
    const int i = (blockIdx.x * blockDim.x + threadIdx.x) * 4;
    float4 v = *(const float4*)(x + i);
    *(float4*)(out + i) = v;
    *(__half2*)(g_x + i)     = __floats2half2_rn(v.x, v.y);
    *(__half2*)(g_x + i + 2) = __floats2half2_rn(v.z, v.w);
}

// ---------------------------------------------------------------------------
// W [K][N] fp32 -> transposed fp16 g_w[widx] as [n][k]
// ---------------------------------------------------------------------------
__global__ void conv_w(const float* __restrict__ W, int widx)
{
    __shared__ float t[32][33];
    const int k0 = blockIdx.y * 32, n0 = blockIdx.x * 32;
    const int tx = threadIdx.x, ty = threadIdx.y;
#pragma unroll
    for (int i = 0; i < 4; i++)
        t[ty + i * 8][tx] = W[(size_t)(k0 + ty + i * 8) * DM + n0 + tx];
    __syncthreads();
    __half* p = g_w[widx];
#pragma unroll
    for (int i = 0; i < 4; i++)
        p[(size_t)(n0 + ty + i * 8) * DM + k0 + tx] = __float2half(t[tx][ty + i * 8]);
}

// ---------------------------------------------------------------------------
// fp16 HMMA GEMM. MODE 0: fused QKV dense (z=0/1/2), gated, Q/8.
// MODE 3: O-proj on COMPACTED ctx rows; scatter out[tok] = ctx@Wo + bo.
// CTA 128x128, BK=32, 8 warps (2x4). 80B pitch (conflict-free ldmatrix).
// ---------------------------------------------------------------------------
#define TILE_B 10240                      // 128*40*2 bytes
#define STAGE_B (2 * TILE_B)              // 20480
#define GSMEM_TOT (2 * STAGE_B)           // 40960

template <int MODE>
__global__ __launch_bounds__(256, 2) void gemm_mma(
    const float* __restrict__ bias0, const float* __restrict__ bias1,
    const float* __restrict__ bias2, const int* __restrict__ gate,
    float* __restrict__ Cout)
{
    extern __shared__ char smem[];
    const uint32_t sb = smem_u32(smem);
    const int tid = threadIdx.x;
    const int wid = tid >> 5;
    const int lane = tid & 31;
    const int wm = wid >> 2;
    const int wn = wid & 3;
    const int n0 = blockIdx.x * 128;

    int m0, bb = 0, nact = 0, jbase = 0;
    if (MODE == 3) {
        bb = blockIdx.z;
        nact = g_nact[bb];
        jbase = blockIdx.y * 128;
        if (jbase >= nact) return;
        m0 = bb * S_ + jbase;
    } else {
        m0 = blockIdx.y * 128;
    }
    const int z = (MODE == 0) ? blockIdx.z : 3;

    const __half* A = (MODE == 3) ? g_c : g_x;
    const __half* Bw = g_w[z];
    const float* bias = (MODE == 3) ? bias0 : (z == 0 ? bias0 : (z == 1 ? bias1 : bias2));
    __half* Oq = nullptr;
    if (MODE == 0) Oq = (z == 0) ? g_q : (z == 1) ? g_k : g_v;

    float acc[4][4][4];
#pragma unroll
    for (int i = 0; i < 4; i++)
#pragma unroll
        for (int j = 0; j < 4; j++)
#pragma unroll
            for (int e = 0; e < 4; e++) acc[i][j][e] = 0.f;

    const int lrow = tid >> 1;
    const int lc0 = (tid & 1) * 2;

    auto load_stage = [&](int st, int kc) {
        const int k0 = kc * 32;
        const uint32_t sbase = sb + st * STAGE_B;
        const size_t goA = (size_t)(m0 + lrow) * DM + k0;
        const size_t goB = (size_t)(n0 + lrow) * DM + k0;
#pragma unroll
        for (int c = 0; c < 2; c++) {
            const int ch = lc0 + c;
            const uint32_t so = lrow * 80 + ch * 16;
            cp16(sbase + so,          A + goA + ch * 8);
            cp16(sbase + TILE_B + so, Bw + goB + ch * 8);
        }
    };

    const int aRowOff = lane & 15;
    const int aColB0 = ((lane >> 4) << 3) * 2;
    const int bRowOff = (lane & 7) + ((lane >> 4) << 3);
    const int bColB0 = (((lane >> 3) & 1) << 3) * 2;

    load_stage(0, 0);
    CP_COMMIT();
    CP_WAIT0();
    __syncthreads();

    const int NCH = DM / 32;
    for (int kc = 0; kc < NCH; kc++) {
        const int cur = kc & 1;
        if (kc + 1 < NCH) { load_stage(1 - cur, kc + 1); CP_COMMIT(); }

        const uint32_t stb = sb + cur * STAGE_B;
#pragma unroll
        for (int ks = 0; ks < 2; ks++) {
            uint32_t a[4][4], bfr[4][2];
            const int kB = ks * 32;
#pragma unroll
            for (int mf = 0; mf < 4; mf++) {
                const uint32_t ra = (wm * 64 + mf * 16 + aRowOff) * 80 + kB + aColB0;
                ldsm_x4(a[mf], stb + ra);
            }
#pragma unroll
            for (int np = 0; np < 2; np++) {
                const uint32_t rb = (wn * 32 + np * 16 + bRowOff) * 80 + kB + bColB0;
                uint32_t t[4];
                ldsm_x4(t, stb + TILE_B + rb);
                bfr[np * 2][0] = t[0]; bfr[np * 2][1] = t[1];
                bfr[np * 2 + 1][0] = t[2]; bfr[np * 2 + 1][1] = t[3];
            }
#pragma unroll
            for (int mf = 0; mf < 4; mf++)
#pragma unroll
                for (int nf = 0; nf < 4; nf++)
                    mma_f16(acc[mf][nf], a[mf], bfr[nf]);
        }
        if (kc + 1 < NCH) { CP_WAIT0(); __syncthreads(); }
    }

    const float qs = (MODE == 0 && z == 0) ? 0.125f : 1.0f;
#pragma unroll
    for (int mf = 0; mf < 4; mf++) {
#pragma unroll
        for (int half = 0; half < 2; half++) {
            const int rl = wm * 64 + mf * 16 + (lane >> 2) + half * 8;
#pragma unroll
            for (int nf = 0; nf < 4; nf++) {
                const int col = n0 + wn * 32 + nf * 8 + ((lane & 3) << 1);
                float v0 = acc[mf][nf][half * 2 + 0] + bias[col];
                float v1 = acc[mf][nf][half * 2 + 1] + bias[col + 1];
                if (MODE == 0) {
                    const int r = m0 + rl;
                    const float gm = (float)gate[r] * qs;
                    *(__half2*)(Oq + (size_t)r * DM + col) =
                        __floats2half2_rn(v0 * gm, v1 * gm);
                } else {
                    const int j = jbase + rl;
                    if (j < nact) {
                        const int tok = g_idx[bb * S_ + j];
                        float2 o; o.x = v0; o.y = v1;
                        *(float2*)(Cout + (size_t)(bb * S_ + tok) * DM + col) = o;
                    }
                }
            }
        }
    }
}

// ---------------------------------------------------------------------------
// fp16 mma.sync flash attention, gate-compacted query rows. Keys dense.
// smem (fp16, pitch 72 elems = 144B): Q [0,18432);
// stages at 18432 + st*18432: K +0, V +9216.
// ---------------------------------------------------------------------------
#define AT_STG0  18432
#define AT_STGSZ 18432
#define AT_SMEM  (AT_STG0 + 2 * AT_STGSZ)   // 55296
#define PITCHB   144

__device__ __forceinline__ void prefetch_kv(uint32_t sb, int b, int kt, int st,
                                            int dcol, int tid)
{
    const uint32_t stg = sb + AT_STG0 + st * AT_STGSZ;
    const int gb = b * S_ + kt * 64;
#pragma unroll
    for (int t = 0; t < 4; t++) {
        const __half* src = (t < 2) ? g_k : g_v;
        const int arr = t >> 1;
        const int rem = (tid + t * 256) - arr * 512;   // 0..511
        const int row = rem >> 3, ch = rem & 7;
        cp16(stg + arr * 9216 + row * PITCHB + ch * 16,
             src + (size_t)(gb + row) * DM + dcol + ch * 8);
    }
}

__global__ __launch_bounds__(256, 2) void attn_mma()
{
    extern __shared__ char smem[];
    const uint32_t sb = smem_u32(smem);
    const int tid = threadIdx.x, wid = tid >> 5, lane = tid & 31;
    const int qt = blockIdx.x, h = blockIdx.y, b = blockIdx.z;
    const int nact = g_nact[b];
    if (qt * 128 >= nact) return;
    const int dcol = h * HD;

    // Q tile (gathered via g_idx) + stage 0 K/V
#pragma unroll
    for (int t = 0; t < 4; t++) {
        const int rem = tid + t * 256;                 // 0..1023
        const int row = rem >> 3, ch = rem & 7;
        int j = qt * 128 + row;
        if (j >= nact) j = nact - 1;
        const int tok = g_idx[b * S_ + j];
        cp16(sb + row * PITCHB + ch * 16,
             g_q + (size_t)(b * S_ + tok) * DM + dcol + ch * 8);
    }
    prefetch_kv(sb, b, 0, 0, dcol, tid);
    CP_COMMIT();
    CP_WAIT0();
    __syncthreads();

    // Q A-fragments
    uint32_t qa[4][4];
    {
        const int aRow = lane & 15;
        const int aCol = (lane >> 4) * 16;
#pragma unroll
        for (int kk = 0; kk < 4; kk++)
            ldsm_x4(qa[kk], sb + (wid * 16 + aRow) * PITCHB + kk * 32 + aCol);
    }

    float Oc[8][4];
#pragma unroll
    for (int j = 0; j < 8; j++)
#pragma unroll
        for (int e = 0; e < 4; e++) Oc[j][e] = 0.f;
    float mr0 = -1e30f, mr1 = -1e30f, lr0 = 0.f, lr1 = 0.f;

    const int bRowK = (lane & 7) + ((lane >> 4) << 3);
    const int bColK = ((lane >> 3) & 1) * 16;
    const int vRow = (lane & 7) + (((lane >> 3) & 1) << 3);
    const int vColB = ((lane >> 4) << 3) * 2;

    for (int kt = 0; kt < 32; kt++) {
        if (kt + 1 < 32) {
            prefetch_kv(sb, b, kt + 1, (kt + 1) & 1, dcol, tid);
            CP_COMMIT();
            CP_WAIT1();
        } else {
            CP_WAIT0();
        }
        __syncthreads();
        const uint32_t stg = sb + AT_STG0 + (kt & 1) * AT_STGSZ;

        // ---- S = Q K^T ----
        float sacc[8][4];
#pragma unroll
        for (int j = 0; j < 8; j++)
#pragma unroll
            for (int e = 0; e < 4; e++) sacc[j][e] = 0.f;

#pragma unroll
        for (int kg = 0; kg < 4; kg++) {
#pragma unroll
            for (int kk = 0; kk < 4; kk++) {
                const uint32_t rb = (kg * 16 + bRowK) * PITCHB + kk * 32 + bColK;
                uint32_t t[4];
                ldsm_x4(t, stg + rb);
                uint32_t b0[2] = {t[0], t[1]}, b1[2] = {t[2], t[3]};
                mma_f16(sacc[2 * kg],     qa[kk], b0);
                mma_f16(sacc[2 * kg + 1], qa[kk], b1);
            }
        }

        // ---- online softmax ----
        float cm0 = sacc[0][0], cm1 = sacc[0][2];
#pragma unroll
        for (int j = 0; j < 8; j++) {
            cm0 = fmaxf(cm0, fmaxf(sacc[j][0], sacc[j][1]));
            cm1 = fmaxf(cm1, fmaxf(sacc[j][2], sacc[j][3]));
        }
        cm0 = fmaxf(cm0, __shfl_xor_sync(0xffffffffu, cm0, 1));
        cm0 = fmaxf(cm0, __shfl_xor_sync(0xffffffffu, cm0, 2));
        cm1 = fmaxf(cm1, __shfl_xor_sync(0xffffffffu, cm1, 1));
        cm1 = fmaxf(cm1, __shfl_xor_sync(0xffffffffu, cm1, 2));
        const float mn0 = fmaxf(mr0, cm0);
        const float mn1 = fmaxf(mr1, cm1);
        const float cr0 = __expf(mr0 - mn0);
        const float cr1 = __expf(mr1 - mn1);
        mr0 = mn0; mr1 = mn1;
#pragma unroll
        for (int j = 0; j < 8; j++) {
            Oc[j][0] *= cr0; Oc[j][1] *= cr0;
            Oc[j][2] *= cr1; Oc[j][3] *= cr1;
        }
        float sum0 = 0.f, sum1 = 0.f;
#pragma unroll
        for (int j = 0; j < 8; j++) {
            sacc[j][0] = __expf(sacc[j][0] - mn0);
            sacc[j][1] = __expf(sacc[j][1] - mn0);
            sacc[j][2] = __expf(sacc[j][2] - mn1);
            sacc[j][3] = __expf(sacc[j][3] - mn1);
            sum0 += sacc[j][0] + sacc[j][1];
            sum1 += sacc[j][2] + sacc[j][3];
        }
        sum0 += __shfl_xor_sync(0xffffffffu, sum0, 1);
        sum0 += __shfl_xor_sync(0xffffffffu, sum0, 2);
        sum1 += __shfl_xor_sync(0xffffffffu, sum1, 1);
        sum1 += __shfl_xor_sync(0xffffffffu, sum1, 2);
        lr0 = lr0 * cr0 + sum0;
        lr1 = lr1 * cr1 + sum1;

        // ---- O += P V ----
#pragma unroll
        for (int kk2 = 0; kk2 < 4; kk2++) {
            // P A-frag order: {(r,k0-7),(r+8,k0-7),(r,k8-15),(r+8,k8-15)}
            uint32_t ap[4];
#pragma unroll
            for (int f = 0; f < 2; f++) {
                const float* p = sacc[2 * kk2 + f];
                ap[2 * f]     = pack2h(p[0], p[1]);
                ap[2 * f + 1] = pack2h(p[2], p[3]);
            }
#pragma unroll
            for (int ng2 = 0; ng2 < 4; ng2++) {
                const uint32_t rv = (kk2 * 16 + vRow) * PITCHB + ng2 * 32 + vColB;
                uint32_t t[4];
                ldsm_x4t(t, stg + 9216 + rv);
                uint32_t b0[2] = {t[0], t[1]}, b1[2] = {t[2], t[3]};
                mma_f16(Oc[2 * ng2],     ap, b0);
                mma_f16(Oc[2 * ng2 + 1], ap, b1);
            }
        }
        __syncthreads();
    }

    // ---- epilogue: normalize, store ctx fp16 at COMPACTED rows ----
    const float inv0 = 1.f / lr0;
    const float inv1 = 1.f / lr1;
    const int jl = wid * 16 + (lane >> 2);
    const int j0 = qt * 128 + jl;
    const int j1 = j0 + 8;
#pragma unroll
    for (int j = 0; j < 8; j++) {
        const int col = dcol + j * 8 + ((lane & 3) << 1);
        if (j0 < nact)
            *(__half2*)(g_c + (size_t)(b * S_ + j0) * DM + col) =
                __floats2half2_rn(Oc[j][0] * inv0, Oc[j][1] * inv0);
        if (j1 < nact)
            *(__half2*)(g_c + (size_t)(b * S_ + j1) * DM + col) =
                __floats2half2_rn(Oc[j][2] * inv1, Oc[j][3] * inv1);
    }
}

// ---------------------------------------------------------------------------
extern "C" void kernel_launch(void* const* d_in, const int* in_sizes, int n_in,
                              void* d_out, int out_size)
{
    const float* x    = (const float*)d_in[0];
    const int*   gate = (const int*)  d_in[1];
    const float* Wq   = (const float*)d_in[2];
    const float* bq   = (const float*)d_in[3];
    const float* Wk   = (const float*)d_in[4];
    const float* bk   = (const float*)d_in[5];
    const float* Wv   = (const float*)d_in[6];
    const float* bv   = (const float*)d_in[7];
    const float* Wo   = (const float*)d_in[8];
    const float* bo   = (const float*)d_in[9];
    float* out = (float*)d_out;

    cudaFuncSetAttribute(gemm_mma<0>, cudaFuncAttributeMaxDynamicSharedMemorySize, GSMEM_TOT);
    cudaFuncSetAttribute(gemm_mma<3>, cudaFuncAttributeMaxDynamicSharedMemorySize, GSMEM_TOT);
    cudaFuncSetAttribute(attn_mma, cudaFuncAttributeMaxDynamicSharedMemorySize, AT_SMEM);

    build_idx<<<B_, 256>>>(gate);
    conv_x<<<MTOT * DM / 1024, 256>>>(x, out);
    conv_w<<<dim3(32, 32), dim3(32, 8)>>>(Wq, 0);
    conv_w<<<dim3(32, 32), dim3(32, 8)>>>(Wk, 1);
    conv_w<<<dim3(32, 32), dim3(32, 8)>>>(Wv, 2);
    conv_w<<<dim3(32, 32), dim3(32, 8)>>>(Wo, 3);

    gemm_mma<0><<<dim3(DM / 128, MTOT / 128, 3), 256, GSMEM_TOT>>>(
        bq, bk, bv, gate, nullptr);

    attn_mma<<<dim3(S_ / 128, HEADS, B_), 256, AT_SMEM>>>();

    gemm_mma<3><<<dim3(DM / 128, S_ / 128, B_), 256, GSMEM_TOT>>>(
        bo, nullptr, nullptr, gate, out);
}

// round 9
// speedup vs baseline: 27.2524x; 1.4092x over previous
#include <cuda_runtime.h>
#include <cuda_fp16.h>
#include <cstdint>
#include <cstddef>

#define DM 1024
#define HEADS 16
#define HD 64
#define B_ 2
#define S_ 2048
#define MTOT 4096   // B*S

// ---------------------------------------------------------------------------
// Scratch (__device__ globals). q/k/v/ctx stored COMPACTED (active rows only).
// ---------------------------------------------------------------------------
__device__ __half g_x[MTOT * DM];
__device__ __half g_q[MTOT * DM];   // pre-scaled by 1/8
__device__ __half g_k[MTOT * DM];
__device__ __half g_v[MTOT * DM];
__device__ __half g_c[MTOT * DM];
__device__ __half g_w[4][DM * DM];  // W^T, [n][k]
__device__ int g_nact[B_];
__device__ int g_idx[B_ * S_];

// ---------------------------------------------------------------------------
// sm_100-safe PTX helpers
// ---------------------------------------------------------------------------
__device__ __forceinline__ uint32_t smem_u32(const void* p) {
    uint32_t a;
    asm("{ .reg .u64 t; cvta.to.shared.u64 t, %1; cvt.u32.u64 %0, t; }"
        : "=r"(a) : "l"(p));
    return a;
}
__device__ __forceinline__ void ldsm_x4(uint32_t* r, uint32_t addr) {
    asm volatile("ldmatrix.sync.aligned.m8n8.x4.shared.b16 {%0,%1,%2,%3}, [%4];"
                 : "=r"(r[0]), "=r"(r[1]), "=r"(r[2]), "=r"(r[3]) : "r"(addr));
}
__device__ __forceinline__ void ldsm_x4t(uint32_t* r, uint32_t addr) {
    asm volatile("ldmatrix.sync.aligned.m8n8.x4.trans.shared.b16 {%0,%1,%2,%3}, [%4];"
                 : "=r"(r[0]), "=r"(r[1]), "=r"(r[2]), "=r"(r[3]) : "r"(addr));
}
__device__ __forceinline__ void mma_f16(float* d, const uint32_t* a, const uint32_t* b) {
    asm volatile(
        "mma.sync.aligned.m16n8k16.row.col.f32.f16.f16.f32 "
        "{%0,%1,%2,%3},{%4,%5,%6,%7},{%8,%9},{%0,%1,%2,%3};"
        : "+f"(d[0]), "+f"(d[1]), "+f"(d[2]), "+f"(d[3])
        : "r"(a[0]), "r"(a[1]), "r"(a[2]), "r"(a[3]), "r"(b[0]), "r"(b[1]));
}
__device__ __forceinline__ void cp16(uint32_t s, const void* g) {
    asm volatile("cp.async.cg.shared.global [%0], [%1], 16;" :: "r"(s), "l"(g));
}
#define CP_COMMIT() asm volatile("cp.async.commit_group;" ::: "memory")
#define CP_WAIT0()  asm volatile("cp.async.wait_group 0;" ::: "memory")
#define CP_WAIT1()  asm volatile("cp.async.wait_group 1;" ::: "memory")

__device__ __forceinline__ uint32_t pack2h(float lo, float hi) {
    uint32_t r;
    asm("cvt.rn.f16x2.f32 %0, %1, %2;" : "=r"(r) : "f"(hi), "f"(lo));
    return r;
}

// ---------------------------------------------------------------------------
// Gate compaction
// ---------------------------------------------------------------------------
__global__ void build_idx(const int* __restrict__ gate)
{
    const int b = blockIdx.x;
    const int tid = threadIdx.x;
    __shared__ int cnt[256];
    const int base = b * S_ + tid * 8;
    int gv[8];
    int c = 0;
#pragma unroll
    for (int i = 0; i < 8; i++) { gv[i] = gate[base + i]; c += gv[i]; }
    cnt[tid] = c;
    __syncthreads();
    for (int off = 1; off < 256; off <<= 1) {
        int t = (tid >= off) ? cnt[tid - off] : 0;
        __syncthreads();
        cnt[tid] += t;
        __syncthreads();
    }
    int o = cnt[tid] - c;
    if (tid == 255) g_nact[b] = cnt[255];
#pragma unroll
    for (int i = 0; i < 8; i++)
        if (gv[i]) g_idx[b * S_ + (o++)] = tid * 8 + i;
}

// ---------------------------------------------------------------------------
// x -> fp16 scratch, and out = x (inactive rows keep x; active overwritten)
// ---------------------------------------------------------------------------
__global__ void conv_x(const float* __restrict__ x, float* __restrict__ out)
{
    const int i = (blockIdx.x * blockDim.x + threadIdx.x) * 4;
    float4 v = *(const float4*)(x + i);
    *(float4*)(out + i) = v;
    *(__half2*)(g_x + i)     = __floats2half2_rn(v.x, v.y);
    *(__half2*)(g_x + i + 2) = __floats2half2_rn(v.z, v.w);
}

// ---------------------------------------------------------------------------
// W [K][N] fp32 -> transposed fp16 g_w[z] as [n][k]. grid.z selects W.
// ---------------------------------------------------------------------------
__global__ void conv_w(const float* __restrict__ W0, const float* __restrict__ W1,
                       const float* __restrict__ W2, const float* __restrict__ W3)
{
    __shared__ float t[32][33];
    const int z = blockIdx.z;
    const float* W = (z == 0) ? W0 : (z == 1) ? W1 : (z == 2) ? W2 : W3;
    const int k0 = blockIdx.y * 32, n0 = blockIdx.x * 32;
    const int tx = threadIdx.x, ty = threadIdx.y;
#pragma unroll
    for (int i = 0; i < 4; i++)
        t[ty + i * 8][tx] = W[(size_t)(k0 + ty + i * 8) * DM + n0 + tx];
    __syncthreads();
    __half* p = g_w[z];
#pragma unroll
    for (int i = 0; i < 4; i++)
        p[(size_t)(n0 + ty + i * 8) * DM + k0 + tx] = __float2half(t[tx][ty + i * 8]);
}

// ---------------------------------------------------------------------------
// fp16 HMMA GEMM over COMPACTED rows.
// MODE 0: QKV. grid = (DM/128, B_*16, 3); y = batch*16 + jtile; z = q/k/v.
//         A rows gathered via g_idx from g_x; q/k/v stored compacted (g=1).
// MODE 3: O-proj. grid = (DM/128, 16, B_). ctx compacted -> scatter to out.
// ---------------------------------------------------------------------------
#define TILE_B 10240
#define STAGE_B (2 * TILE_B)
#define GSMEM_TOT (2 * STAGE_B)           // 40960

template <int MODE>
__global__ __launch_bounds__(256, 2) void gemm_mma(
    const float* __restrict__ bias0, const float* __restrict__ bias1,
    const float* __restrict__ bias2, float* __restrict__ Cout)
{
    extern __shared__ char smem[];
    const uint32_t sb = smem_u32(smem);
    const int tid = threadIdx.x;
    const int wid = tid >> 5;
    const int lane = tid & 31;
    const int wm = wid >> 2;
    const int wn = wid & 3;
    const int n0 = blockIdx.x * 128;

    int bb, jbase;
    if (MODE == 0) { bb = blockIdx.y >> 4; jbase = (blockIdx.y & 15) * 128; }
    else           { bb = blockIdx.z;      jbase = blockIdx.y * 128; }
    const int nact = g_nact[bb];
    if (jbase >= nact) return;
    const int z = (MODE == 0) ? blockIdx.z : 3;

    const __half* Bw = g_w[z];
    const float* bias = (MODE == 3) ? bias0 : (z == 0 ? bias0 : (z == 1 ? bias1 : bias2));
    __half* Oq = nullptr;
    if (MODE == 0) Oq = (z == 0) ? g_q : (z == 1) ? g_k : g_v;

    float acc[4][4][4];
#pragma unroll
    for (int i = 0; i < 4; i++)
#pragma unroll
        for (int j = 0; j < 4; j++)
#pragma unroll
            for (int e = 0; e < 4; e++) acc[i][j][e] = 0.f;

    const int lrow = tid >> 1;
    const int lc0 = (tid & 1) * 2;

    // per-thread A row (fixed across k-chunks)
    size_t rowA;
    {
        int j = jbase + lrow;
        if (j >= nact) j = nact - 1;
        if (MODE == 0) rowA = (size_t)(bb * S_ + g_idx[bb * S_ + j]) * DM;
        else           rowA = (size_t)(bb * S_ + j) * DM;
    }
    const __half* A = (MODE == 3) ? g_c : g_x;
    const size_t rowB = (size_t)(n0 + lrow) * DM;

    auto load_stage = [&](int st, int kc) {
        const int k0 = kc * 32;
        const uint32_t sbase = sb + st * STAGE_B;
#pragma unroll
        for (int c = 0; c < 2; c++) {
            const int ch = lc0 + c;
            const uint32_t so = lrow * 80 + ch * 16;
            cp16(sbase + so,          A + rowA + k0 + ch * 8);
            cp16(sbase + TILE_B + so, Bw + rowB + k0 + ch * 8);
        }
    };

    const int aRowOff = lane & 15;
    const int aColB0 = ((lane >> 4) << 3) * 2;
    const int bRowOff = (lane & 7) + ((lane >> 4) << 3);
    const int bColB0 = (((lane >> 3) & 1) << 3) * 2;

    load_stage(0, 0);
    CP_COMMIT();
    CP_WAIT0();
    __syncthreads();

    const int NCH = DM / 32;
    for (int kc = 0; kc < NCH; kc++) {
        const int cur = kc & 1;
        if (kc + 1 < NCH) { load_stage(1 - cur, kc + 1); CP_COMMIT(); }

        const uint32_t stb = sb + cur * STAGE_B;
#pragma unroll
        for (int ks = 0; ks < 2; ks++) {
            uint32_t a[4][4], bfr[4][2];
            const int kB = ks * 32;
#pragma unroll
            for (int mf = 0; mf < 4; mf++)
                ldsm_x4(a[mf], stb + (wm * 64 + mf * 16 + aRowOff) * 80 + kB + aColB0);
#pragma unroll
            for (int np = 0; np < 2; np++) {
                uint32_t t[4];
                ldsm_x4(t, stb + TILE_B + (wn * 32 + np * 16 + bRowOff) * 80 + kB + bColB0);
                bfr[np * 2][0] = t[0]; bfr[np * 2][1] = t[1];
                bfr[np * 2 + 1][0] = t[2]; bfr[np * 2 + 1][1] = t[3];
            }
#pragma unroll
            for (int mf = 0; mf < 4; mf++)
#pragma unroll
                for (int nf = 0; nf < 4; nf++)
                    mma_f16(acc[mf][nf], a[mf], bfr[nf]);
        }
        if (kc + 1 < NCH) { CP_WAIT0(); __syncthreads(); }
    }

    const float qs = (MODE == 0 && z == 0) ? 0.125f : 1.0f;
#pragma unroll
    for (int mf = 0; mf < 4; mf++) {
#pragma unroll
        for (int half = 0; half < 2; half++) {
            const int rl = wm * 64 + mf * 16 + (lane >> 2) + half * 8;
            const int j = jbase + rl;
            if (j >= nact) continue;
#pragma unroll
            for (int nf = 0; nf < 4; nf++) {
                const int col = n0 + wn * 32 + nf * 8 + ((lane & 3) << 1);
                float v0 = acc[mf][nf][half * 2 + 0] + bias[col];
                float v1 = acc[mf][nf][half * 2 + 1] + bias[col + 1];
                if (MODE == 0) {
                    *(__half2*)(Oq + (size_t)(bb * S_ + j) * DM + col) =
                        __floats2half2_rn(v0 * qs, v1 * qs);
                } else {
                    const int tok = g_idx[bb * S_ + j];
                    float2 o; o.x = v0; o.y = v1;
                    *(float2*)(Cout + (size_t)(bb * S_ + tok) * DM + col) = o;
                }
            }
        }
    }
}

// ---------------------------------------------------------------------------
// fp16 mma.sync flash attention. Queries AND keys compacted.
// Inactive keys folded analytically: init m = 0, l = (S - nact).
// Last partial key tile masked to -1e30.
// ---------------------------------------------------------------------------
#define AT_STG0  18432
#define AT_STGSZ 18432
#define AT_SMEM  (AT_STG0 + 2 * AT_STGSZ)   // 55296
#define PITCHB   144

__device__ __forceinline__ void prefetch_kv(uint32_t sb, int b, int kt, int st,
                                            int dcol, int tid, int nact)
{
    const uint32_t stg = sb + AT_STG0 + st * AT_STGSZ;
#pragma unroll
    for (int t = 0; t < 4; t++) {
        const __half* src = (t < 2) ? g_k : g_v;
        const int arr = t >> 1;
        const int rem = (tid + t * 256) - arr * 512;   // 0..511
        const int row = rem >> 3, ch = rem & 7;
        int j = kt * 64 + row;
        if (j >= nact) j = nact - 1;
        cp16(stg + arr * 9216 + row * PITCHB + ch * 16,
             src + (size_t)(b * S_ + j) * DM + dcol + ch * 8);
    }
}

__global__ __launch_bounds__(256, 2) void attn_mma()
{
    extern __shared__ char smem[];
    const uint32_t sb = smem_u32(smem);
    const int tid = threadIdx.x, wid = tid >> 5, lane = tid & 31;
    const int qt = blockIdx.x, h = blockIdx.y, b = blockIdx.z;
    const int nact = g_nact[b];
    if (qt * 128 >= nact) return;
    const int dcol = h * HD;
    const int nkt = (nact + 63) >> 6;

    // Q tile (compacted, dense) + stage 0 K/V
#pragma unroll
    for (int t = 0; t < 4; t++) {
        const int rem = tid + t * 256;
        const int row = rem >> 3, ch = rem & 7;
        int j = qt * 128 + row;
        if (j >= nact) j = nact - 1;
        cp16(sb + row * PITCHB + ch * 16,
             g_q + (size_t)(b * S_ + j) * DM + dcol + ch * 8);
    }
    prefetch_kv(sb, b, 0, 0, dcol, tid, nact);
    CP_COMMIT();
    CP_WAIT0();
    __syncthreads();

    uint32_t qa[4][4];
    {
        const int aRow = lane & 15;
        const int aCol = (lane >> 4) * 16;
#pragma unroll
        for (int kk = 0; kk < 4; kk++)
            ldsm_x4(qa[kk], sb + (wid * 16 + aRow) * PITCHB + kk * 32 + aCol);
    }

    float Oc[8][4];
#pragma unroll
    for (int j = 0; j < 8; j++)
#pragma unroll
        for (int e = 0; e < 4; e++) Oc[j][e] = 0.f;
    // analytic fold of (S - nact) zero-score, zero-value keys:
    float mr0 = 0.f, mr1 = 0.f;
    float lr0 = (float)(S_ - nact), lr1 = (float)(S_ - nact);

    const int bRowK = (lane & 7) + ((lane >> 4) << 3);
    const int bColK = ((lane >> 3) & 1) * 16;
    const int vRow = (lane & 7) + (((lane >> 3) & 1) << 3);
    const int vColB = ((lane >> 4) << 3) * 2;

    for (int kt = 0; kt < nkt; kt++) {
        if (kt + 1 < nkt) {
            prefetch_kv(sb, b, kt + 1, (kt + 1) & 1, dcol, tid, nact);
            CP_COMMIT();
            CP_WAIT1();
        } else {
            CP_WAIT0();
        }
        __syncthreads();
        const uint32_t stg = sb + AT_STG0 + (kt & 1) * AT_STGSZ;

        // ---- S = Q K^T ----
        float sacc[8][4];
#pragma unroll
        for (int j = 0; j < 8; j++)
#pragma unroll
            for (int e = 0; e < 4; e++) sacc[j][e] = 0.f;

#pragma unroll
        for (int kg = 0; kg < 4; kg++) {
#pragma unroll
            for (int kk = 0; kk < 4; kk++) {
                uint32_t t[4];
                ldsm_x4(t, stg + (kg * 16 + bRowK) * PITCHB + kk * 32 + bColK);
                uint32_t b0[2] = {t[0], t[1]}, b1[2] = {t[2], t[3]};
                mma_f16(sacc[2 * kg],     qa[kk], b0);
                mma_f16(sacc[2 * kg + 1], qa[kk], b1);
            }
        }

        // mask padded keys in last tile (C-frag col = (lane&3)*2 + (e&1))
        if (kt == nkt - 1) {
            const int kbase = kt * 64;
#pragma unroll
            for (int jj = 0; jj < 8; jj++) {
                const int kc0 = kbase + (jj >> 1) * 16 + (jj & 1) * 8 + ((lane & 3) << 1);
                if (kc0 >= nact)     { sacc[jj][0] = -1e30f; sacc[jj][2] = -1e30f; }
                if (kc0 + 1 >= nact) { sacc[jj][1] = -1e30f; sacc[jj][3] = -1e30f; }
            }
        }

        // ---- online softmax ----
        float cm0 = sacc[0][0], cm1 = sacc[0][2];
#pragma unroll
        for (int j = 0; j < 8; j++) {
            cm0 = fmaxf(cm0, fmaxf(sacc[j][0], sacc[j][1]));
            cm1 = fmaxf(cm1, fmaxf(sacc[j][2], sacc[j][3]));
        }
        cm0 = fmaxf(cm0, __shfl_xor_sync(0xffffffffu, cm0, 1));
        cm0 = fmaxf(cm0, __shfl_xor_sync(0xffffffffu, cm0, 2));
        cm1 = fmaxf(cm1, __shfl_xor_sync(0xffffffffu, cm1, 1));
        cm1 = fmaxf(cm1, __shfl_xor_sync(0xffffffffu, cm1, 2));
        const float mn0 = fmaxf(mr0, cm0);
        const float mn1 = fmaxf(mr1, cm1);
        const float cr0 = __expf(mr0 - mn0);
        const float cr1 = __expf(mr1 - mn1);
        mr0 = mn0; mr1 = mn1;
#pragma unroll
        for (int j = 0; j < 8; j++) {
            Oc[j][0] *= cr0; Oc[j][1] *= cr0;
            Oc[j][2] *= cr1; Oc[j][3] *= cr1;
        }
        float sum0 = 0.f, sum1 = 0.f;
#pragma unroll
        for (int j = 0; j < 8; j++) {
            sacc[j][0] = __expf(sacc[j][0] - mn0);
            sacc[j][1] = __expf(sacc[j][1] - mn0);
            sacc[j][2] = __expf(sacc[j][2] - mn1);
            sacc[j][3] = __expf(sacc[j][3] - mn1);
            sum0 += sacc[j][0] + sacc[j][1];
            sum1 += sacc[j][2] + sacc[j][3];
        }
        sum0 += __shfl_xor_sync(0xffffffffu, sum0, 1);
        sum0 += __shfl_xor_sync(0xffffffffu, sum0, 2);
        sum1 += __shfl_xor_sync(0xffffffffu, sum1, 1);
        sum1 += __shfl_xor_sync(0xffffffffu, sum1, 2);
        lr0 = lr0 * cr0 + sum0;
        lr1 = lr1 * cr1 + sum1;

        // ---- O += P V ----
#pragma unroll
        for (int kk2 = 0; kk2 < 4; kk2++) {
            uint32_t ap[4];
#pragma unroll
            for (int f = 0; f < 2; f++) {
                const float* p = sacc[2 * kk2 + f];
                ap[2 * f]     = pack2h(p[0], p[1]);
                ap[2 * f + 1] = pack2h(p[2], p[3]);
            }
#pragma unroll
            for (int ng2 = 0; ng2 < 4; ng2++) {
                uint32_t t[4];
                ldsm_x4t(t, stg + 9216 + (kk2 * 16 + vRow) * PITCHB + ng2 * 32 + vColB);
                uint32_t b0[2] = {t[0], t[1]}, b1[2] = {t[2], t[3]};
                mma_f16(Oc[2 * ng2],     ap, b0);
                mma_f16(Oc[2 * ng2 + 1], ap, b1);
            }
        }
        __syncthreads();
    }

    // ---- epilogue: normalize, store ctx fp16 at compacted rows ----
    const float inv0 = 1.f / lr0;
    const float inv1 = 1.f / lr1;
    const int jl = wid * 16 + (lane >> 2);
    const int j0 = qt * 128 + jl;
    const int j1 = j0 + 8;
#pragma unroll
    for (int j = 0; j < 8; j++) {
        const int col = dcol + j * 8 + ((lane & 3) << 1);
        if (j0 < nact)
            *(__half2*)(g_c + (size_t)(b * S_ + j0) * DM + col) =
                __floats2half2_rn(Oc[j][0] * inv0, Oc[j][1] * inv0);
        if (j1 < nact)
            *(__half2*)(g_c + (size_t)(b * S_ + j1) * DM + col) =
                __floats2half2_rn(Oc[j][2] * inv1, Oc[j][3] * inv1);
    }
}

// ---------------------------------------------------------------------------
extern "C" void kernel_launch(void* const* d_in, const int* in_sizes, int n_in,
                              void* d_out, int out_size)
{
    const float* x    = (const float*)d_in[0];
    const int*   gate = (const int*)  d_in[1];
    const float* Wq   = (const float*)d_in[2];
    const float* bq   = (const float*)d_in[3];
    const float* Wk   = (const float*)d_in[4];
    const float* bk   = (const float*)d_in[5];
    const float* Wv   = (const float*)d_in[6];
    const float* bv   = (const float*)d_in[7];
    const float* Wo   = (const float*)d_in[8];
    const float* bo   = (const float*)d_in[9];
    float* out = (float*)d_out;

    cudaFuncSetAttribute(gemm_mma<0>, cudaFuncAttributeMaxDynamicSharedMemorySize, GSMEM_TOT);
    cudaFuncSetAttribute(gemm_mma<3>, cudaFuncAttributeMaxDynamicSharedMemorySize, GSMEM_TOT);
    cudaFuncSetAttribute(attn_mma, cudaFuncAttributeMaxDynamicSharedMemorySize, AT_SMEM);

    build_idx<<<B_, 256>>>(gate);
    conv_x<<<MTOT * DM / 1024, 256>>>(x, out);
    conv_w<<<dim3(32, 32, 4), dim3(32, 8)>>>(Wq, Wk, Wv, Wo);

    gemm_mma<0><<<dim3(DM / 128, B_ * 16, 3), 256, GSMEM_TOT>>>(bq, bk, bv, nullptr);

    attn_mma<<<dim3(S_ / 128, HEADS, B_), 256, AT_SMEM>>>();

    gemm_mma<3><<<dim3(DM / 128, S_ / 128, B_), 256, GSMEM_TOT>>>(bo, nullptr, nullptr, out);
}

// round 10
// speedup vs baseline: 28.4521x; 1.0440x over previous
#include <cuda_runtime.h>
#include <cuda_fp16.h>
#include <cstdint>
#include <cstddef>

#define DM 1024
#define HEADS 16
#define HD 64
#define B_ 2
#define S_ 2048
#define MTOT 4096   // B*S

// ---------------------------------------------------------------------------
// Scratch (__device__ globals). q/k/v/ctx stored COMPACTED (active rows only).
// ---------------------------------------------------------------------------
__device__ __half g_x[MTOT * DM];
__device__ __half g_q[MTOT * DM];   // pre-scaled by 1/8
__device__ __half g_k[MTOT * DM];
__device__ __half g_v[MTOT * DM];
__device__ __half g_c[MTOT * DM];
__device__ __half g_w[4][DM * DM];  // W^T, [n][k]
__device__ int g_nact[B_];
__device__ int g_idx[B_ * S_];

// ---------------------------------------------------------------------------
// sm_100-safe PTX helpers
// ---------------------------------------------------------------------------
__device__ __forceinline__ uint32_t smem_u32(const void* p) {
    uint32_t a;
    asm("{ .reg .u64 t; cvta.to.shared.u64 t, %1; cvt.u32.u64 %0, t; }"
        : "=r"(a) : "l"(p));
    return a;
}
__device__ __forceinline__ void ldsm_x4(uint32_t* r, uint32_t addr) {
    asm volatile("ldmatrix.sync.aligned.m8n8.x4.shared.b16 {%0,%1,%2,%3}, [%4];"
                 : "=r"(r[0]), "=r"(r[1]), "=r"(r[2]), "=r"(r[3]) : "r"(addr));
}
__device__ __forceinline__ void ldsm_x4t(uint32_t* r, uint32_t addr) {
    asm volatile("ldmatrix.sync.aligned.m8n8.x4.trans.shared.b16 {%0,%1,%2,%3}, [%4];"
                 : "=r"(r[0]), "=r"(r[1]), "=r"(r[2]), "=r"(r[3]) : "r"(addr));
}
__device__ __forceinline__ void mma_f16(float* d, const uint32_t* a, const uint32_t* b) {
    asm volatile(
        "mma.sync.aligned.m16n8k16.row.col.f32.f16.f16.f32 "
        "{%0,%1,%2,%3},{%4,%5,%6,%7},{%8,%9},{%0,%1,%2,%3};"
        : "+f"(d[0]), "+f"(d[1]), "+f"(d[2]), "+f"(d[3])
        : "r"(a[0]), "r"(a[1]), "r"(a[2]), "r"(a[3]), "r"(b[0]), "r"(b[1]));
}
__device__ __forceinline__ void cp16(uint32_t s, const void* g) {
    asm volatile("cp.async.cg.shared.global [%0], [%1], 16;" :: "r"(s), "l"(g));
}
#define CP_COMMIT() asm volatile("cp.async.commit_group;" ::: "memory")
#define CP_WAIT0()  asm volatile("cp.async.wait_group 0;" ::: "memory")
#define CP_WAIT1()  asm volatile("cp.async.wait_group 1;" ::: "memory")

__device__ __forceinline__ uint32_t pack2h(float lo, float hi) {
    uint32_t r;
    asm("cvt.rn.f16x2.f32 %0, %1, %2;" : "=r"(r) : "f"(hi), "f"(lo));
    return r;
}

// ---------------------------------------------------------------------------
// Gate compaction
// ---------------------------------------------------------------------------
__global__ void build_idx(const int* __restrict__ gate)
{
    const int b = blockIdx.x;
    const int tid = threadIdx.x;
    __shared__ int cnt[256];
    const int base = b * S_ + tid * 8;
    int gv[8];
    int c = 0;
#pragma unroll
    for (int i = 0; i < 8; i++) { gv[i] = gate[base + i]; c += gv[i]; }
    cnt[tid] = c;
    __syncthreads();
    for (int off = 1; off < 256; off <<= 1) {
        int t = (tid >= off) ? cnt[tid - off] : 0;
        __syncthreads();
        cnt[tid] += t;
        __syncthreads();
    }
    int o = cnt[tid] - c;
    if (tid == 255) g_nact[b] = cnt[255];
#pragma unroll
    for (int i = 0; i < 8; i++)
        if (gv[i]) g_idx[b * S_ + (o++)] = tid * 8 + i;
}

// ---------------------------------------------------------------------------
// x -> fp16 scratch, and out = x (inactive rows keep x; active overwritten)
// ---------------------------------------------------------------------------
__global__ void conv_x(const float* __restrict__ x, float* __restrict__ out)
{
    const int i = (blockIdx.x * blockDim.x + threadIdx.x) * 4;
    float4 v = *(const float4*)(x + i);
    *(float4*)(out + i) = v;
    *(__half2*)(g_x + i)     = __floats2half2_rn(v.x, v.y);
    *(__half2*)(g_x + i + 2) = __floats2half2_rn(v.z, v.w);
}

// ---------------------------------------------------------------------------
// W [K][N] fp32 -> transposed fp16 g_w[z] as [n][k]. grid.z selects W.
// ---------------------------------------------------------------------------
__global__ void conv_w(const float* __restrict__ W0, const float* __restrict__ W1,
                       const float* __restrict__ W2, const float* __restrict__ W3)
{
    __shared__ float t[32][33];
    const int z = blockIdx.z;
    const float* W = (z == 0) ? W0 : (z == 1) ? W1 : (z == 2) ? W2 : W3;
    const int k0 = blockIdx.y * 32, n0 = blockIdx.x * 32;
    const int tx = threadIdx.x, ty = threadIdx.y;
#pragma unroll
    for (int i = 0; i < 4; i++)
        t[ty + i * 8][tx] = W[(size_t)(k0 + ty + i * 8) * DM + n0 + tx];
    __syncthreads();
    __half* p = g_w[z];
#pragma unroll
    for (int i = 0; i < 4; i++)
        p[(size_t)(n0 + ty + i * 8) * DM + k0 + tx] = __float2half(t[tx][ty + i * 8]);
}

// ---------------------------------------------------------------------------
// fp16 HMMA GEMM over COMPACTED rows, 3-stage cp.async pipeline.
// MODE 0: QKV. grid = (DM/128, B_*16, 3); y = batch*16 + jtile; z = q/k/v.
// MODE 3: O-proj. grid = (DM/128, 16, B_). ctx compacted -> scatter to out.
// ---------------------------------------------------------------------------
#define TILE_B 10240
#define STAGE_B (2 * TILE_B)              // 20480
#define GSMEM_TOT (3 * STAGE_B)           // 61440

template <int MODE>
__global__ __launch_bounds__(256, 2) void gemm_mma(
    const float* __restrict__ bias0, const float* __restrict__ bias1,
    const float* __restrict__ bias2, float* __restrict__ Cout)
{
    extern __shared__ char smem[];
    const uint32_t sb = smem_u32(smem);
    const int tid = threadIdx.x;
    const int wid = tid >> 5;
    const int lane = tid & 31;
    const int wm = wid >> 2;
    const int wn = wid & 3;
    const int n0 = blockIdx.x * 128;

    int bb, jbase;
    if (MODE == 0) { bb = blockIdx.y >> 4; jbase = (blockIdx.y & 15) * 128; }
    else           { bb = blockIdx.z;      jbase = blockIdx.y * 128; }
    const int nact = g_nact[bb];
    if (jbase >= nact) return;
    const int z = (MODE == 0) ? blockIdx.z : 3;

    const __half* Bw = g_w[z];
    const float* bias = (MODE == 3) ? bias0 : (z == 0 ? bias0 : (z == 1 ? bias1 : bias2));
    __half* Oq = nullptr;
    if (MODE == 0) Oq = (z == 0) ? g_q : (z == 1) ? g_k : g_v;

    float acc[4][4][4];
#pragma unroll
    for (int i = 0; i < 4; i++)
#pragma unroll
        for (int j = 0; j < 4; j++)
#pragma unroll
            for (int e = 0; e < 4; e++) acc[i][j][e] = 0.f;

    const int lrow = tid >> 1;
    const int lc0 = (tid & 1) * 2;

    // per-thread A row (fixed across k-chunks)
    size_t rowA;
    {
        int j = jbase + lrow;
        if (j >= nact) j = nact - 1;
        if (MODE == 0) rowA = (size_t)(bb * S_ + g_idx[bb * S_ + j]) * DM;
        else           rowA = (size_t)(bb * S_ + j) * DM;
    }
    const __half* A = (MODE == 3) ? g_c : g_x;
    const size_t rowB = (size_t)(n0 + lrow) * DM;

    auto load_stage = [&](int st, int kc) {
        const int k0 = kc * 32;
        const uint32_t sbase = sb + st * STAGE_B;
#pragma unroll
        for (int c = 0; c < 2; c++) {
            const int ch = lc0 + c;
            const uint32_t so = lrow * 80 + ch * 16;
            cp16(sbase + so,          A + rowA + k0 + ch * 8);
            cp16(sbase + TILE_B + so, Bw + rowB + k0 + ch * 8);
        }
    };

    const int aRowOff = lane & 15;
    const int aColB0 = ((lane >> 4) << 3) * 2;
    const int bRowOff = (lane & 7) + ((lane >> 4) << 3);
    const int bColB0 = (((lane >> 3) & 1) << 3) * 2;

    // 3-stage pipeline prologue
    load_stage(0, 0); CP_COMMIT();
    load_stage(1, 1); CP_COMMIT();

    const int NCH = DM / 32;
    int stcur = 0;
    for (int kc = 0; kc < NCH; kc++) {
        // retire group kc (issued 2 iterations ago): 2 groups in flight -> WAIT1
        if (kc + 1 < NCH) CP_WAIT1(); else CP_WAIT0();
        __syncthreads();   // publishes stage kc; also: all warps done with stage kc-1
        if (kc + 2 < NCH) {
            const int stn = (stcur + 2 >= 3) ? stcur - 1 : stcur + 2;
            load_stage(stn, kc + 2);
            CP_COMMIT();
        }

        const uint32_t stb = sb + stcur * STAGE_B;
#pragma unroll
        for (int ks = 0; ks < 2; ks++) {
            uint32_t a[4][4], bfr[4][2];
            const int kB = ks * 32;
#pragma unroll
            for (int mf = 0; mf < 4; mf++)
                ldsm_x4(a[mf], stb + (wm * 64 + mf * 16 + aRowOff) * 80 + kB + aColB0);
#pragma unroll
            for (int np = 0; np < 2; np++) {
                uint32_t t[4];
                ldsm_x4(t, stb + TILE_B + (wn * 32 + np * 16 + bRowOff) * 80 + kB + bColB0);
                bfr[np * 2][0] = t[0]; bfr[np * 2][1] = t[1];
                bfr[np * 2 + 1][0] = t[2]; bfr[np * 2 + 1][1] = t[3];
            }
#pragma unroll
            for (int mf = 0; mf < 4; mf++)
#pragma unroll
                for (int nf = 0; nf < 4; nf++)
                    mma_f16(acc[mf][nf], a[mf], bfr[nf]);
        }
        stcur = (stcur + 1 == 3) ? 0 : stcur + 1;
    }

    const float qs = (MODE == 0 && z == 0) ? 0.125f : 1.0f;
#pragma unroll
    for (int mf = 0; mf < 4; mf++) {
#pragma unroll
        for (int half = 0; half < 2; half++) {
            const int rl = wm * 64 + mf * 16 + (lane >> 2) + half * 8;
            const int j = jbase + rl;
            if (j >= nact) continue;
#pragma unroll
            for (int nf = 0; nf < 4; nf++) {
                const int col = n0 + wn * 32 + nf * 8 + ((lane & 3) << 1);
                float v0 = acc[mf][nf][half * 2 + 0] + bias[col];
                float v1 = acc[mf][nf][half * 2 + 1] + bias[col + 1];
                if (MODE == 0) {
                    *(__half2*)(Oq + (size_t)(bb * S_ + j) * DM + col) =
                        __floats2half2_rn(v0 * qs, v1 * qs);
                } else {
                    const int tok = g_idx[bb * S_ + j];
                    float2 o; o.x = v0; o.y = v1;
                    *(float2*)(Cout + (size_t)(bb * S_ + tok) * DM + col) = o;
                }
            }
        }
    }
}

// ---------------------------------------------------------------------------
// fp16 mma.sync flash attention. Queries AND keys compacted.
// Inactive keys folded analytically: init m = 0, l = (S - nact).
// Last partial key tile masked to -1e30.
// ---------------------------------------------------------------------------
#define AT_STG0  18432
#define AT_STGSZ 18432
#define AT_SMEM  (AT_STG0 + 2 * AT_STGSZ)   // 55296
#define PITCHB   144

__device__ __forceinline__ void prefetch_kv(uint32_t sb, int b, int kt, int st,
                                            int dcol, int tid, int nact)
{
    const uint32_t stg = sb + AT_STG0 + st * AT_STGSZ;
#pragma unroll
    for (int t = 0; t < 4; t++) {
        const __half* src = (t < 2) ? g_k : g_v;
        const int arr = t >> 1;
        const int rem = (tid + t * 256) - arr * 512;   // 0..511
        const int row = rem >> 3, ch = rem & 7;
        int j = kt * 64 + row;
        if (j >= nact) j = nact - 1;
        cp16(stg + arr * 9216 + row * PITCHB + ch * 16,
             src + (size_t)(b * S_ + j) * DM + dcol + ch * 8);
    }
}

__global__ __launch_bounds__(256, 2) void attn_mma()
{
    extern __shared__ char smem[];
    const uint32_t sb = smem_u32(smem);
    const int tid = threadIdx.x, wid = tid >> 5, lane = tid & 31;
    const int qt = blockIdx.x, h = blockIdx.y, b = blockIdx.z;
    const int nact = g_nact[b];
    if (qt * 128 >= nact) return;
    const int dcol = h * HD;
    const int nkt = (nact + 63) >> 6;

    // Q tile (compacted, dense) + stage 0 K/V
#pragma unroll
    for (int t = 0; t < 4; t++) {
        const int rem = tid + t * 256;
        const int row = rem >> 3, ch = rem & 7;
        int j = qt * 128 + row;
        if (j >= nact) j = nact - 1;
        cp16(sb + row * PITCHB + ch * 16,
             g_q + (size_t)(b * S_ + j) * DM + dcol + ch * 8);
    }
    prefetch_kv(sb, b, 0, 0, dcol, tid, nact);
    CP_COMMIT();
    CP_WAIT0();
    __syncthreads();

    uint32_t qa[4][4];
    {
        const int aRow = lane & 15;
        const int aCol = (lane >> 4) * 16;
#pragma unroll
        for (int kk = 0; kk < 4; kk++)
            ldsm_x4(qa[kk], sb + (wid * 16 + aRow) * PITCHB + kk * 32 + aCol);
    }

    float Oc[8][4];
#pragma unroll
    for (int j = 0; j < 8; j++)
#pragma unroll
        for (int e = 0; e < 4; e++) Oc[j][e] = 0.f;
    // analytic fold of (S - nact) zero-score, zero-value keys:
    float mr0 = 0.f, mr1 = 0.f;
    float lr0 = (float)(S_ - nact), lr1 = (float)(S_ - nact);

    const int bRowK = (lane & 7) + ((lane >> 4) << 3);
    const int bColK = ((lane >> 3) & 1) * 16;
    const int vRow = (lane & 7) + (((lane >> 3) & 1) << 3);
    const int vColB = ((lane >> 4) << 3) * 2;

    for (int kt = 0; kt < nkt; kt++) {
        if (kt + 1 < nkt) {
            prefetch_kv(sb, b, kt + 1, (kt + 1) & 1, dcol, tid, nact);
            CP_COMMIT();
            CP_WAIT1();
        } else {
            CP_WAIT0();
        }
        __syncthreads();
        const uint32_t stg = sb + AT_STG0 + (kt & 1) * AT_STGSZ;

        // ---- S = Q K^T ----
        float sacc[8][4];
#pragma unroll
        for (int j = 0; j < 8; j++)
#pragma unroll
            for (int e = 0; e < 4; e++) sacc[j][e] = 0.f;

#pragma unroll
        for (int kg = 0; kg < 4; kg++) {
#pragma unroll
            for (int kk = 0; kk < 4; kk++) {
                uint32_t t[4];
                ldsm_x4(t, stg + (kg * 16 + bRowK) * PITCHB + kk * 32 + bColK);
                uint32_t b0[2] = {t[0], t[1]}, b1[2] = {t[2], t[3]};
                mma_f16(sacc[2 * kg],     qa[kk], b0);
                mma_f16(sacc[2 * kg + 1], qa[kk], b1);
            }
        }

        // mask padded keys in last tile (C-frag col = (lane&3)*2 + (e&1))
        if (kt == nkt - 1) {
            const int kbase = kt * 64;
#pragma unroll
            for (int jj = 0; jj < 8; jj++) {
                const int kc0 = kbase + (jj >> 1) * 16 + (jj & 1) * 8 + ((lane & 3) << 1);
                if (kc0 >= nact)     { sacc[jj][0] = -1e30f; sacc[jj][2] = -1e30f; }
                if (kc0 + 1 >= nact) { sacc[jj][1] = -1e30f; sacc[jj][3] = -1e30f; }
            }
        }

        // ---- online softmax ----
        float cm0 = sacc[0][0], cm1 = sacc[0][2];
#pragma unroll
        for (int j = 0; j < 8; j++) {
            cm0 = fmaxf(cm0, fmaxf(sacc[j][0], sacc[j][1]));
            cm1 = fmaxf(cm1, fmaxf(sacc[j][2], sacc[j][3]));
        }
        cm0 = fmaxf(cm0, __shfl_xor_sync(0xffffffffu, cm0, 1));
        cm0 = fmaxf(cm0, __shfl_xor_sync(0xffffffffu, cm0, 2));
        cm1 = fmaxf(cm1, __shfl_xor_sync(0xffffffffu, cm1, 1));
        cm1 = fmaxf(cm1, __shfl_xor_sync(0xffffffffu, cm1, 2));
        const float mn0 = fmaxf(mr0, cm0);
        const float mn1 = fmaxf(mr1, cm1);
        const float cr0 = __expf(mr0 - mn0);
        const float cr1 = __expf(mr1 - mn1);
        mr0 = mn0; mr1 = mn1;
#pragma unroll
        for (int j = 0; j < 8; j++) {
            Oc[j][0] *= cr0; Oc[j][1] *= cr0;
            Oc[j][2] *= cr1; Oc[j][3] *= cr1;
        }
        float sum0 = 0.f, sum1 = 0.f;
#pragma unroll
        for (int j = 0; j < 8; j++) {
            sacc[j][0] = __expf(sacc[j][0] - mn0);
            sacc[j][1] = __expf(sacc[j][1] - mn0);
            sacc[j][2] = __expf(sacc[j][2] - mn1);
            sacc[j][3] = __expf(sacc[j][3] - mn1);
            sum0 += sacc[j][0] + sacc[j][1];
            sum1 += sacc[j][2] + sacc[j][3];
        }
        sum0 += __shfl_xor_sync(0xffffffffu, sum0, 1);
        sum0 += __shfl_xor_sync(0xffffffffu, sum0, 2);
        sum1 += __shfl_xor_sync(0xffffffffu, sum1, 1);
        sum1 += __shfl_xor_sync(0xffffffffu, sum1, 2);
        lr0 = lr0 * cr0 + sum0;
        lr1 = lr1 * cr1 + sum1;

        // ---- O += P V ----
#pragma unroll
        for (int kk2 = 0; kk2 < 4; kk2++) {
            uint32_t ap[4];
#pragma unroll
            for (int f = 0; f < 2; f++) {
                const float* p = sacc[2 * kk2 + f];
                ap[2 * f]     = pack2h(p[0], p[1]);
                ap[2 * f + 1] = pack2h(p[2], p[3]);
            }
#pragma unroll
            for (int ng2 = 0; ng2 < 4; ng2++) {
                uint32_t t[4];
                ldsm_x4t(t, stg + 9216 + (kk2 * 16 + vRow) * PITCHB + ng2 * 32 + vColB);
                uint32_t b0[2] = {t[0], t[1]}, b1[2] = {t[2], t[3]};
                mma_f16(Oc[2 * ng2],     ap, b0);
                mma_f16(Oc[2 * ng2 + 1], ap, b1);
            }
        }
        __syncthreads();
    }

    // ---- epilogue: normalize, store ctx fp16 at compacted rows ----
    const float inv0 = 1.f / lr0;
    const float inv1 = 1.f / lr1;
    const int jl = wid * 16 + (lane >> 2);
    const int j0 = qt * 128 + jl;
    const int j1 = j0 + 8;
#pragma unroll
    for (int j = 0; j < 8; j++) {
        const int col = dcol + j * 8 + ((lane & 3) << 1);
        if (j0 < nact)
            *(__half2*)(g_c + (size_t)(b * S_ + j0) * DM + col) =
                __floats2half2_rn(Oc[j][0] * inv0, Oc[j][1] * inv0);
        if (j1 < nact)
            *(__half2*)(g_c + (size_t)(b * S_ + j1) * DM + col) =
                __floats2half2_rn(Oc[j][2] * inv1, Oc[j][3] * inv1);
    }
}

// ---------------------------------------------------------------------------
extern "C" void kernel_launch(void* const* d_in, const int* in_sizes, int n_in,
                              void* d_out, int out_size)
{
    const float* x    = (const float*)d_in[0];
    const int*   gate = (const int*)  d_in[1];
    const float* Wq   = (const float*)d_in[2];
    const float* bq   = (const float*)d_in[3];
    const float* Wk   = (const float*)d_in[4];
    const float* bk   = (const float*)d_in[5];
    const float* Wv   = (const float*)d_in[6];
    const float* bv   = (const float*)d_in[7];
    const float* Wo   = (const float*)d_in[8];
    const float* bo   = (const float*)d_in[9];
    float* out = (float*)d_out;

    cudaFuncSetAttribute(gemm_mma<0>, cudaFuncAttributeMaxDynamicSharedMemorySize, GSMEM_TOT);
    cudaFuncSetAttribute(gemm_mma<3>, cudaFuncAttributeMaxDynamicSharedMemorySize, GSMEM_TOT);
    cudaFuncSetAttribute(attn_mma, cudaFuncAttributeMaxDynamicSharedMemorySize, AT_SMEM);

    build_idx<<<B_, 256>>>(gate);
    conv_x<<<MTOT * DM / 1024, 256>>>(x, out);
    conv_w<<<dim3(32, 32, 4), dim3(32, 8)>>>(Wq, Wk, Wv, Wo);

    gemm_mma<0><<<dim3(DM / 128, B_ * 16, 3), 256, GSMEM_TOT>>>(bq, bk, bv, nullptr);

    attn_mma<<<dim3(S_ / 128, HEADS, B_), 256, AT_SMEM>>>();

    gemm_mma<3><<<dim3(DM / 128, S_ / 128, B_), 256, GSMEM_TOT>>>(bo, nullptr, nullptr, out);
}